// round 3
// baseline (speedup 1.0000x reference)
#include <cuda_runtime.h>
#include <cuda_bf16.h>

// Problem constants
#define B_   4
#define T_   2048
#define C_   1024
#define H_   16
#define D_   64
#define TC3  (3 * C_)

// Scratch (allocation-free rule: __device__ globals, referenced directly
// from device code — no cudaGetSymbolAddress on the host side).
__device__ float g_qkv[B_ * T_ * TC3];   // [B,T,3C]  k|q|v
__device__ float g_att[B_ * T_ * C_];    // [B,T,C] attention output

// ---------------------------------------------------------------------------
// SGEMM: C = A[MxK] @ B[KxN], row-major, M,N,K multiples of 128/8.
// 128x128 block, BK=8, 256 threads, 8x8 per thread.
// MODE: 0 = A from param, write param C; 1 = A param, write g_qkv;
//       2 = A g_att, write param C.
// ---------------------------------------------------------------------------
#define BM 128
#define BN 128
#define BK 8

template <int MODE>
__global__ __launch_bounds__(256) void sgemm_kernel(
    const float* __restrict__ Ap, const float* __restrict__ Bm,
    float* __restrict__ Cp, int M, int N, int K)
{
    __shared__ float As[BK][BM];
    __shared__ float Bs[BK][BN];

    const float* A = (MODE == 2) ? (const float*)g_att : Ap;
    float* C = (MODE == 1) ? (float*)g_qkv : Cp;

    const int tid = threadIdx.x;
    const int tr = tid >> 4;        // 0..15 (row group)
    const int tc = tid & 15;        // 0..15 (col group)
    const int bx = blockIdx.x, by = blockIdx.y;

    const float* Ab = A + by * BM * K;
    const float* Bb = Bm + bx * BN;

    const int arow = tid >> 1;            // 0..127
    const int acol = (tid & 1) << 2;      // 0 or 4
    const int brow = tid >> 5;            // 0..7
    const int bcol = (tid & 31) << 2;     // 0..124

    float acc[8][8];
#pragma unroll
    for (int i = 0; i < 8; i++)
#pragma unroll
        for (int j = 0; j < 8; j++) acc[i][j] = 0.f;

    for (int k0 = 0; k0 < K; k0 += BK) {
        float4 a4 = *(const float4*)(Ab + arow * K + k0 + acol);
        As[acol + 0][arow] = a4.x;
        As[acol + 1][arow] = a4.y;
        As[acol + 2][arow] = a4.z;
        As[acol + 3][arow] = a4.w;
        float4 b4 = *(const float4*)(Bb + (k0 + brow) * N + bcol);
        *(float4*)&Bs[brow][bcol] = b4;
        __syncthreads();

#pragma unroll
        for (int k = 0; k < BK; k++) {
            float4 a0 = *(const float4*)&As[k][tr * 8];
            float4 a1 = *(const float4*)&As[k][tr * 8 + 4];
            float4 b0 = *(const float4*)&Bs[k][tc * 8];
            float4 b1 = *(const float4*)&Bs[k][tc * 8 + 4];
            float ra[8] = {a0.x, a0.y, a0.z, a0.w, a1.x, a1.y, a1.z, a1.w};
            float rb[8] = {b0.x, b0.y, b0.z, b0.w, b1.x, b1.y, b1.z, b1.w};
#pragma unroll
            for (int i = 0; i < 8; i++)
#pragma unroll
                for (int j = 0; j < 8; j++)
                    acc[i][j] += ra[i] * rb[j];
        }
        __syncthreads();
    }

    const int crow0 = by * BM + tr * 8;
    const int ccol0 = bx * BN + tc * 8;
#pragma unroll
    for (int i = 0; i < 8; i++) {
        float4 c0 = {acc[i][0], acc[i][1], acc[i][2], acc[i][3]};
        float4 c1 = {acc[i][4], acc[i][5], acc[i][6], acc[i][7]};
        *(float4*)&C[(crow0 + i) * N + ccol0]     = c0;
        *(float4*)&C[(crow0 + i) * N + ccol0 + 4] = c1;
    }
}

// ---------------------------------------------------------------------------
// Flash attention (fp32, causal). Reads g_qkv, writes g_att.
// Block = (b, h, 128-query tile). 256 threads = 16x16 grid;
// each thread owns 8 query rows x 4 key cols (S) and 8 rows x 4 dims (O).
// qkv layout: [B,T,3C] with segments k(0), q(C), v(2C); head h -> cols h*64..
// Scale C^-0.5 = 1/32 folded into Q load.
// Qt is stored TRANSPOSED [64 x 128] so the S-loop reads 8 query values of
// one k-step with two LDS.128. Kt likewise [64 x 64] k-major.
// ---------------------------------------------------------------------------
#define FQ 128
#define FK 64
#define QTSTR 132   // Qt row stride (128 cols + 4 pad floats)
#define KTSTR 68    // Kt row stride (64 cols + 4 pad)
#define VSTR 68
#define PSTR 65
// dyn smem floats: Qt 64*132=8448 | Kt 64*68=4352 | Vs 64*68=4352 | Ps 128*65=8320
#define FLASH_SMEM_FLOATS (64*QTSTR + 64*KTSTR + 64*VSTR + 128*PSTR)
#define FLASH_SMEM_BYTES  (FLASH_SMEM_FLOATS * 4)

__global__ __launch_bounds__(256, 2) void flash_kernel()
{
    extern __shared__ float sm[];
    float* Qt = sm;                       // [64][QTSTR]  Qt[k][q] = Q[q][k]*scale
    float* Kt = Qt + 64 * QTSTR;          // [64][KTSTR]  Kt[k][j] = K[j][k]
    float* Vs = Kt + 64 * KTSTR;          // [64][VSTR]   Vs[j][d]
    float* Ps = Vs + 64 * VSTR;           // [128][PSTR]

    const float* qkv = (const float*)g_qkv;
    float* att = (float*)g_att;

    const int tid = threadIdx.x;
    const int tr = tid >> 4;   // 0..15: query row group (8 rows each)
    const int tc = tid & 15;   // 0..15: key/dim col group (4 each)
    const int h = blockIdx.y;
    const int b = blockIdx.z;
    // big q-tiles first (more work under causal mask) for better tail behavior
    const int q0 = (gridDim.x - 1 - blockIdx.x) * FQ;

    const int base = b * T_ * TC3;
    const int hoff = h * D_;
    const float scale = 0.03125f;   // 1024^-0.5

    // Load Q tile [128 x 64] -> transposed smem [64 x 128], pre-scaled
#pragma unroll
    for (int i = 0; i < 8; i++) {
        int idx = i * 256 + tid;         // 0..2047
        int r   = idx >> 4;              // query row 0..127
        int c4  = (idx & 15) << 2;       // k 0..60
        float4 v = *(const float4*)(qkv + base + (q0 + r) * TC3 + C_ + hoff + c4);
        Qt[(c4 + 0) * QTSTR + r] = v.x * scale;
        Qt[(c4 + 1) * QTSTR + r] = v.y * scale;
        Qt[(c4 + 2) * QTSTR + r] = v.z * scale;
        Qt[(c4 + 3) * QTSTR + r] = v.w * scale;
    }

    float o[8][4];
    float m[8], l[8];
#pragma unroll
    for (int a = 0; a < 8; a++) {
        m[a] = -1e30f; l[a] = 0.f;
#pragma unroll
        for (int bb = 0; bb < 4; bb++) o[a][bb] = 0.f;
    }

    const int jend = q0 + FQ;  // keys beyond q0+FQ-1 are always masked
    for (int j0 = 0; j0 < jend; j0 += FK) {
        // Load K (transposed to k-major) and V tiles [64 x 64]
#pragma unroll
        for (int i = 0; i < 4; i++) {
            int idx = i * 256 + tid;     // 0..1023
            int r   = idx >> 4;          // key row 0..63
            int c4  = (idx & 15) << 2;   // k/d 0..60
            const float* gp = qkv + base + (j0 + r) * TC3;
            float4 kv = *(const float4*)(gp + hoff + c4);          // k segment
            Kt[(c4 + 0) * KTSTR + r] = kv.x;
            Kt[(c4 + 1) * KTSTR + r] = kv.y;
            Kt[(c4 + 2) * KTSTR + r] = kv.z;
            Kt[(c4 + 3) * KTSTR + r] = kv.w;
            float4 vv = *(const float4*)(gp + 2 * C_ + hoff + c4); // v segment
            *(float4*)(Vs + r * VSTR + c4) = vv;
        }
        __syncthreads();

        // S = Q @ K^T  (8x4 per thread), k-major smem
        float s[8][4];
#pragma unroll
        for (int a = 0; a < 8; a++)
#pragma unroll
            for (int bb = 0; bb < 4; bb++) s[a][bb] = 0.f;

#pragma unroll 4
        for (int kk = 0; kk < 64; kk++) {
            float4 a0 = *(const float4*)&Qt[kk * QTSTR + tr * 8];
            float4 a1 = *(const float4*)&Qt[kk * QTSTR + tr * 8 + 4];
            float4 b0 = *(const float4*)&Kt[kk * KTSTR + tc * 4];
            float ra[8] = {a0.x, a0.y, a0.z, a0.w, a1.x, a1.y, a1.z, a1.w};
            float rb[4] = {b0.x, b0.y, b0.z, b0.w};
#pragma unroll
            for (int a = 0; a < 8; a++)
#pragma unroll
                for (int bb = 0; bb < 4; bb++)
                    s[a][bb] += ra[a] * rb[bb];
        }

        // Causal mask (only the diagonal-intersecting k-tile needs masking)
        if (j0 + FK > q0) {
#pragma unroll
            for (int a = 0; a < 8; a++) {
                int qi = q0 + tr * 8 + a;
#pragma unroll
                for (int bb = 0; bb < 4; bb++) {
                    int kj = j0 + tc * 4 + bb;
                    if (kj > qi) s[a][bb] = -1e30f;
                }
            }
        }

        // Online softmax (row = 16-lane shfl group)
#pragma unroll
        for (int a = 0; a < 8; a++) {
            float mx = fmaxf(fmaxf(s[a][0], s[a][1]), fmaxf(s[a][2], s[a][3]));
#pragma unroll
            for (int off = 8; off > 0; off >>= 1)
                mx = fmaxf(mx, __shfl_xor_sync(0xffffffffu, mx, off, 16));
            float mn = fmaxf(m[a], mx);
            float alpha = __expf(m[a] - mn);
            m[a] = mn;
            float rs = 0.f;
#pragma unroll
            for (int bb = 0; bb < 4; bb++) {
                float p = __expf(s[a][bb] - mn);
                s[a][bb] = p;
                rs += p;
            }
#pragma unroll
            for (int off = 8; off > 0; off >>= 1)
                rs += __shfl_xor_sync(0xffffffffu, rs, off, 16);
            l[a] = l[a] * alpha + rs;
#pragma unroll
            for (int bb = 0; bb < 4; bb++) o[a][bb] *= alpha;
#pragma unroll
            for (int bb = 0; bb < 4; bb++)
                Ps[(tr * 8 + a) * PSTR + tc * 4 + bb] = s[a][bb];
        }
        __syncthreads();

        // O += P @ V   (thread owns dims tc*4..tc*4+3)
#pragma unroll 8
        for (int kk = 0; kk < 64; kk++) {
            float4 v4 = *(const float4*)(Vs + kk * VSTR + tc * 4);
#pragma unroll
            for (int a = 0; a < 8; a++) {
                float p = Ps[(tr * 8 + a) * PSTR + kk];
                o[a][0] += p * v4.x;
                o[a][1] += p * v4.y;
                o[a][2] += p * v4.z;
                o[a][3] += p * v4.w;
            }
        }
        __syncthreads();
    }

    // Epilogue: normalize and store to g_att[b, q, h*64 + d]
#pragma unroll
    for (int a = 0; a < 8; a++) {
        float inv = 1.f / l[a];
        float4 r;
        r.x = o[a][0] * inv;
        r.y = o[a][1] * inv;
        r.z = o[a][2] * inv;
        r.w = o[a][3] * inv;
        *(float4*)(att + (b * T_ + q0 + tr * 8 + a) * C_ + hoff + tc * 4) = r;
    }
}

// ---------------------------------------------------------------------------
// Launch — minimal host API surface: one attribute set + three launches.
// ---------------------------------------------------------------------------
extern "C" void kernel_launch(void* const* d_in, const int* in_sizes, int n_in,
                              void* d_out, int out_size)
{
    const float* x     = (const float*)d_in[0];   // [B,T,C]
    const float* Wqkv  = (const float*)d_in[1];   // [C,3C]
    const float* Wproj = (const float*)d_in[2];   // [C,C]
    float* out = (float*)d_out;                   // [B,T,C]

    cudaFuncSetAttribute(flash_kernel,
                         cudaFuncAttributeMaxDynamicSharedMemorySize,
                         FLASH_SMEM_BYTES);

    const int M = B_ * T_;  // 8192

    // 1) g_qkv = x @ W_qkv   [8192 x 3072]
    sgemm_kernel<1><<<dim3(3 * C_ / BN, M / BM), 256>>>(x, Wqkv, nullptr,
                                                        M, 3 * C_, C_);

    // 2) flash attention: g_qkv -> g_att [8192 x 1024]
    flash_kernel<<<dim3(T_ / FQ, H_, B_), 256, FLASH_SMEM_BYTES>>>();

    // 3) out = g_att @ W_proj  [8192 x 1024]
    sgemm_kernel<2><<<dim3(C_ / BN, M / BM), 256>>>(nullptr, Wproj, out,
                                                    M, C_, C_);
}

// round 6
// speedup vs baseline: 1.7952x; 1.7952x over previous
#include <cuda_runtime.h>
#include <cstdint>

// Problem constants
#define B_   4
#define T_   2048
#define C_   1024
#define H_   16
#define D_   64
#define TC3  (3 * C_)

// Scratch (allocation-free rule: __device__ globals)
__device__ float g_qkv[B_ * T_ * TC3];     // [B,T,3C]  k|q|v
__device__ float g_att[B_ * T_ * C_];      // [B,T,C]
__device__ float g_WqkvT[TC3 * C_];        // [3C, C]  = W_qkv^T (K-major)
__device__ float g_WprojT[C_ * C_];        // [C, C]   = W_proj^T

// ===========================================================================
// Helpers
// ===========================================================================
__device__ __forceinline__ uint32_t smem_to_u32(const void* p) {
    uint32_t a;
    asm("{ .reg .u64 t; cvta.to.shared.u64 t, %1; cvt.u32.u64 %0, t; }"
        : "=r"(a) : "l"(p));
    return a;
}

__device__ __forceinline__ uint32_t f2tf32(float f) {
    uint32_t r;
    asm("cvt.rna.tf32.f32 %0, %1;" : "=r"(r) : "f"(f));
    return r;
}

__device__ __forceinline__ void ldmx4(uint32_t* r, uint32_t addr) {
    asm volatile("ldmatrix.sync.aligned.m8n8.x4.shared.b16 {%0,%1,%2,%3}, [%4];"
                 : "=r"(r[0]), "=r"(r[1]), "=r"(r[2]), "=r"(r[3]) : "r"(addr));
}

__device__ __forceinline__ void mma_tf32(float* c, const uint32_t* a,
                                         const uint32_t* b) {
    asm volatile(
        "mma.sync.aligned.m16n8k8.row.col.f32.tf32.tf32.f32 "
        "{%0,%1,%2,%3}, {%4,%5,%6,%7}, {%8,%9}, {%0,%1,%2,%3};"
        : "+f"(c[0]), "+f"(c[1]), "+f"(c[2]), "+f"(c[3])
        : "r"(a[0]), "r"(a[1]), "r"(a[2]), "r"(a[3]), "r"(b[0]), "r"(b[1]));
}

#define SWZ(off) ((off) ^ (((off) >> 3) & 0x70))

// ===========================================================================
// Weight transpose: out[c][r] = in[r][c]; in is [R][Cc] row-major.
// ===========================================================================
template <int MODE>
__global__ void transpose_kernel(const float* __restrict__ in, int R, int Cc)
{
    __shared__ float t[32][33];
    float* out = (MODE == 0) ? (float*)g_WqkvT : (float*)g_WprojT;
    const int c0 = blockIdx.x * 32, r0 = blockIdx.y * 32;
#pragma unroll
    for (int j = threadIdx.y; j < 32; j += 8)
        t[j][threadIdx.x] = in[(size_t)(r0 + j) * Cc + c0 + threadIdx.x];
    __syncthreads();
#pragma unroll
    for (int j = threadIdx.y; j < 32; j += 8)
        out[(size_t)(c0 + j) * R + r0 + threadIdx.x] = t[threadIdx.x][j];
}

// ===========================================================================
// Tensor-core tf32 GEMM via mma.sync (arch-independent PTX; runs on the
// Blackwell fallback-HMMA tensor path since tcgen05 PTX is rejected by the
// generic compute_103 target this harness compiles through).
//
// C[M,N] = A[M,K] @ Bt[N,K]^T, both operands K-major.
// CTA 128x128, BK=32 (128B rows, SW128), 256 thr = 8 warps (2M x 4N),
// warp tile 64x32. Double-buffered smem + register prefetch.
// MODE 0: A = param (x),  Bt = g_WqkvT, C = g_qkv
// MODE 1: A = g_att,      Bt = g_WprojT, C = param (out)
// ===========================================================================
#define GBK 32
#define GTILE 16384                  // 128 rows x 128 bytes
#define GSMEM (4 * GTILE)            // A0,B0,A1,B1 = 64 KB

template <int MODE, int N, int K>
__global__ __launch_bounds__(256) void mma_gemm(
    const float* __restrict__ Ap, float* __restrict__ Cp)
{
    extern __shared__ char sm[];
    const uint32_t smem_u32 = smem_to_u32(sm);

    const float* Ag = (MODE == 0) ? Ap : (const float*)g_att;
    const float* Bg = (MODE == 0) ? (const float*)g_WqkvT : (const float*)g_WprojT;
    float* Cg = (MODE == 0) ? (float*)g_qkv : Cp;

    const int tid = threadIdx.x;
    const int lane = tid & 31;
    const int wid = tid >> 5;
    const int warp_m = wid & 1;          // 0..1  (64-row slabs)
    const int warp_n = wid >> 1;         // 0..3  (32-col slabs)
    const int m0 = blockIdx.y * 128;
    const int n0 = blockIdx.x * 128;

    // Fill-slot geometry: slot s in [0,1024): row = s>>3, 16B-chunk = s&7
    const int frow = tid >> 3;           // base row for j=0 (rows advance by 32/j)
    const int ff4  = tid & 7;

    float acc[4][4][4];
#pragma unroll
    for (int i = 0; i < 4; i++)
#pragma unroll
        for (int j = 0; j < 4; j++)
#pragma unroll
            for (int k = 0; k < 4; k++) acc[i][j][k] = 0.f;

    const int NCHUNK = K / GBK;

    // ---- prologue: chunk 0 -> buffer 0
    {
        float4 pa[4], pb[4];
#pragma unroll
        for (int j = 0; j < 4; j++) {
            int row = frow + j * 32;
            pa[j] = *(const float4*)(Ag + (size_t)(m0 + row) * K + ff4 * 4);
            pb[j] = *(const float4*)(Bg + (size_t)(n0 + row) * K + ff4 * 4);
        }
#pragma unroll
        for (int j = 0; j < 4; j++) {
            int row = frow + j * 32;
            uint32_t off = SWZ(row * 128 + ff4 * 16);
            uint4 ta = { f2tf32(pa[j].x), f2tf32(pa[j].y), f2tf32(pa[j].z), f2tf32(pa[j].w) };
            uint4 tb = { f2tf32(pb[j].x), f2tf32(pb[j].y), f2tf32(pb[j].z), f2tf32(pb[j].w) };
            *(uint4*)(sm + off) = ta;
            *(uint4*)(sm + GTILE + off) = tb;
        }
    }
    __syncthreads();

    // ldmatrix lane-address components (constant per thread)
    const int a_row_in_tile = lane & 15;                 // 0..15
    const int a_kblk = (lane >> 4) & 1;                  // 0 or 1 (16B)
    const int b_row_in_pair = ((lane & 16) >> 1) + (lane & 7);  // 0..15
    const int b_kblk = (lane >> 3) & 1;

    for (int i = 0; i < NCHUNK; i++) {
        // Prefetch next chunk
        float4 pa[4], pb[4];
        if (i + 1 < NCHUNK) {
            const int k0 = (i + 1) * GBK;
#pragma unroll
            for (int j = 0; j < 4; j++) {
                int row = frow + j * 32;
                pa[j] = *(const float4*)(Ag + (size_t)(m0 + row) * K + k0 + ff4 * 4);
                pb[j] = *(const float4*)(Bg + (size_t)(n0 + row) * K + k0 + ff4 * 4);
            }
        }

        // Compute on buffer i&1
        const uint32_t Abuf = smem_u32 + (uint32_t)(i & 1) * (2 * GTILE);
        const uint32_t Bbuf = Abuf + GTILE;
#pragma unroll
        for (int ks = 0; ks < 4; ks++) {
            uint32_t afr[4][4];
#pragma unroll
            for (int mt = 0; mt < 4; mt++) {
                int row = warp_m * 64 + mt * 16 + a_row_in_tile;
                uint32_t off = SWZ(row * 128 + ks * 32 + a_kblk * 16);
                ldmx4(afr[mt], Abuf + off);
            }
            uint32_t bfr[2][4];
#pragma unroll
            for (int p = 0; p < 2; p++) {
                int row = warp_n * 32 + p * 16 + b_row_in_pair;
                uint32_t off = SWZ(row * 128 + ks * 32 + b_kblk * 16);
                ldmx4(bfr[p], Bbuf + off);
            }
#pragma unroll
            for (int mt = 0; mt < 4; mt++)
#pragma unroll
                for (int nt = 0; nt < 4; nt++)
                    mma_tf32(acc[mt][nt], afr[mt], &bfr[nt >> 1][(nt & 1) * 2]);
        }
        __syncthreads();

        // Store prefetched chunk into the other buffer
        if (i + 1 < NCHUNK) {
            char* dst = sm + (size_t)((i + 1) & 1) * (2 * GTILE);
#pragma unroll
            for (int j = 0; j < 4; j++) {
                int row = frow + j * 32;
                uint32_t off = SWZ(row * 128 + ff4 * 16);
                uint4 ta = { f2tf32(pa[j].x), f2tf32(pa[j].y), f2tf32(pa[j].z), f2tf32(pa[j].w) };
                uint4 tb = { f2tf32(pb[j].x), f2tf32(pb[j].y), f2tf32(pb[j].z), f2tf32(pb[j].w) };
                *(uint4*)(dst + off) = ta;
                *(uint4*)(dst + GTILE + off) = tb;
            }
            __syncthreads();
        }
    }

    // Epilogue: c0,c1 -> (row g, col 2t, 2t+1); c2,c3 -> row g+8
    const int og = lane >> 2;            // groupID
    const int ot = lane & 3;             // threadID_in_group
#pragma unroll
    for (int mt = 0; mt < 4; mt++) {
        int r0 = m0 + warp_m * 64 + mt * 16 + og;
#pragma unroll
        for (int nt = 0; nt < 4; nt++) {
            int col = n0 + warp_n * 32 + nt * 8 + ot * 2;
            float2 lo = { acc[mt][nt][0], acc[mt][nt][1] };
            float2 hi = { acc[mt][nt][2], acc[mt][nt][3] };
            *(float2*)(Cg + (size_t)r0 * N + col) = lo;
            *(float2*)(Cg + (size_t)(r0 + 8) * N + col) = hi;
        }
    }
}

// ===========================================================================
// Flash attention (fp32, causal) — unchanged from the passing R3 kernel.
// ===========================================================================
#define FQ 128
#define FK 64
#define QTSTR 132
#define KTSTR 68
#define VSTR 68
#define PSTR 65
#define FLASH_SMEM_FLOATS (64*QTSTR + 64*KTSTR + 64*VSTR + 128*PSTR)
#define FLASH_SMEM_BYTES  (FLASH_SMEM_FLOATS * 4)

__global__ __launch_bounds__(256, 2) void flash_kernel()
{
    extern __shared__ float smf[];
    float* Qt = smf;
    float* Kt = Qt + 64 * QTSTR;
    float* Vs = Kt + 64 * KTSTR;
    float* Ps = Vs + 64 * VSTR;

    const float* qkv = (const float*)g_qkv;
    float* att = (float*)g_att;

    const int tid = threadIdx.x;
    const int tr = tid >> 4;
    const int tc = tid & 15;
    const int h = blockIdx.y;
    const int b = blockIdx.z;
    const int q0 = (gridDim.x - 1 - blockIdx.x) * FQ;

    const int base = b * T_ * TC3;
    const int hoff = h * D_;
    const float scale = 0.03125f;

#pragma unroll
    for (int i = 0; i < 8; i++) {
        int idx = i * 256 + tid;
        int r   = idx >> 4;
        int c4  = (idx & 15) << 2;
        float4 v = *(const float4*)(qkv + base + (q0 + r) * TC3 + C_ + hoff + c4);
        Qt[(c4 + 0) * QTSTR + r] = v.x * scale;
        Qt[(c4 + 1) * QTSTR + r] = v.y * scale;
        Qt[(c4 + 2) * QTSTR + r] = v.z * scale;
        Qt[(c4 + 3) * QTSTR + r] = v.w * scale;
    }

    float o[8][4];
    float m[8], l[8];
#pragma unroll
    for (int a = 0; a < 8; a++) {
        m[a] = -1e30f; l[a] = 0.f;
#pragma unroll
        for (int bb = 0; bb < 4; bb++) o[a][bb] = 0.f;
    }

    const int jend = q0 + FQ;
    for (int j0 = 0; j0 < jend; j0 += FK) {
#pragma unroll
        for (int i = 0; i < 4; i++) {
            int idx = i * 256 + tid;
            int r   = idx >> 4;
            int c4  = (idx & 15) << 2;
            const float* gp = qkv + base + (j0 + r) * TC3;
            float4 kv = *(const float4*)(gp + hoff + c4);
            Kt[(c4 + 0) * KTSTR + r] = kv.x;
            Kt[(c4 + 1) * KTSTR + r] = kv.y;
            Kt[(c4 + 2) * KTSTR + r] = kv.z;
            Kt[(c4 + 3) * KTSTR + r] = kv.w;
            float4 vv = *(const float4*)(gp + 2 * C_ + hoff + c4);
            *(float4*)(Vs + r * VSTR + c4) = vv;
        }
        __syncthreads();

        float s[8][4];
#pragma unroll
        for (int a = 0; a < 8; a++)
#pragma unroll
            for (int bb = 0; bb < 4; bb++) s[a][bb] = 0.f;

#pragma unroll 4
        for (int kk = 0; kk < 64; kk++) {
            float4 a0 = *(const float4*)&Qt[kk * QTSTR + tr * 8];
            float4 a1 = *(const float4*)&Qt[kk * QTSTR + tr * 8 + 4];
            float4 b0 = *(const float4*)&Kt[kk * KTSTR + tc * 4];
            float ra[8] = {a0.x, a0.y, a0.z, a0.w, a1.x, a1.y, a1.z, a1.w};
            float rb[4] = {b0.x, b0.y, b0.z, b0.w};
#pragma unroll
            for (int a = 0; a < 8; a++)
#pragma unroll
                for (int bb = 0; bb < 4; bb++)
                    s[a][bb] += ra[a] * rb[bb];
        }

        if (j0 + FK > q0) {
#pragma unroll
            for (int a = 0; a < 8; a++) {
                int qi = q0 + tr * 8 + a;
#pragma unroll
                for (int bb = 0; bb < 4; bb++) {
                    int kj = j0 + tc * 4 + bb;
                    if (kj > qi) s[a][bb] = -1e30f;
                }
            }
        }

#pragma unroll
        for (int a = 0; a < 8; a++) {
            float mx = fmaxf(fmaxf(s[a][0], s[a][1]), fmaxf(s[a][2], s[a][3]));
#pragma unroll
            for (int off = 8; off > 0; off >>= 1)
                mx = fmaxf(mx, __shfl_xor_sync(0xffffffffu, mx, off, 16));
            float mn = fmaxf(m[a], mx);
            float alpha = __expf(m[a] - mn);
            m[a] = mn;
            float rs = 0.f;
#pragma unroll
            for (int bb = 0; bb < 4; bb++) {
                float p = __expf(s[a][bb] - mn);
                s[a][bb] = p;
                rs += p;
            }
#pragma unroll
            for (int off = 8; off > 0; off >>= 1)
                rs += __shfl_xor_sync(0xffffffffu, rs, off, 16);
            l[a] = l[a] * alpha + rs;
#pragma unroll
            for (int bb = 0; bb < 4; bb++) o[a][bb] *= alpha;
#pragma unroll
            for (int bb = 0; bb < 4; bb++)
                Ps[(tr * 8 + a) * PSTR + tc * 4 + bb] = s[a][bb];
        }
        __syncthreads();

#pragma unroll 8
        for (int kk = 0; kk < 64; kk++) {
            float4 v4 = *(const float4*)(Vs + kk * VSTR + tc * 4);
#pragma unroll
            for (int a = 0; a < 8; a++) {
                float p = Ps[(tr * 8 + a) * PSTR + kk];
                o[a][0] += p * v4.x;
                o[a][1] += p * v4.y;
                o[a][2] += p * v4.z;
                o[a][3] += p * v4.w;
            }
        }
        __syncthreads();
    }

#pragma unroll
    for (int a = 0; a < 8; a++) {
        float inv = 1.f / l[a];
        float4 r;
        r.x = o[a][0] * inv;
        r.y = o[a][1] * inv;
        r.z = o[a][2] * inv;
        r.w = o[a][3] * inv;
        *(float4*)(att + (b * T_ + q0 + tr * 8 + a) * C_ + hoff + tc * 4) = r;
    }
}

// ===========================================================================
// Launch
// ===========================================================================
extern "C" void kernel_launch(void* const* d_in, const int* in_sizes, int n_in,
                              void* d_out, int out_size)
{
    const float* x     = (const float*)d_in[0];   // [B,T,C]
    const float* Wqkv  = (const float*)d_in[1];   // [C,3C]
    const float* Wproj = (const float*)d_in[2];   // [C,C]
    float* out = (float*)d_out;                   // [B,T,C]

    cudaFuncSetAttribute(flash_kernel,
                         cudaFuncAttributeMaxDynamicSharedMemorySize,
                         FLASH_SMEM_BYTES);
    cudaFuncSetAttribute(mma_gemm<0, TC3, C_>,
                         cudaFuncAttributeMaxDynamicSharedMemorySize, GSMEM);
    cudaFuncSetAttribute(mma_gemm<1, C_, C_>,
                         cudaFuncAttributeMaxDynamicSharedMemorySize, GSMEM);

    // 0) Transpose weights -> K-major B operands
    transpose_kernel<0><<<dim3(TC3 / 32, C_ / 32), dim3(32, 8)>>>(Wqkv, C_, TC3);
    transpose_kernel<1><<<dim3(C_ / 32, C_ / 32), dim3(32, 8)>>>(Wproj, C_, C_);

    // 1) g_qkv = x @ W_qkv   (tf32 mma.sync)
    mma_gemm<0, TC3, C_><<<dim3(TC3 / 128, (B_ * T_) / 128), 256, GSMEM>>>(x, nullptr);

    // 2) flash attention: g_qkv -> g_att
    flash_kernel<<<dim3(T_ / FQ, H_, B_), 256, FLASH_SMEM_BYTES>>>();

    // 3) out = g_att @ W_proj  (tf32 mma.sync)
    mma_gemm<1, C_, C_><<<dim3(C_ / 128, (B_ * T_) / 128), 256, GSMEM>>>(nullptr, out);
}

// round 10
// speedup vs baseline: 3.0422x; 1.6946x over previous
#include <cuda_runtime.h>
#include <cstdint>

// Problem constants
#define B_   4
#define T_   2048
#define C_   1024
#define H_   16
#define D_   64
#define TC3  (3 * C_)

// Scratch (allocation-free rule: __device__ globals)
__device__ float g_qkv[B_ * T_ * TC3];     // [B,T,3C]  k|q|v
__device__ float g_att[B_ * T_ * C_];      // [B,T,C]
__device__ float g_WqkvT[TC3 * C_];        // [3C, C]  = W_qkv^T (K-major)
__device__ float g_WprojT[C_ * C_];        // [C, C]   = W_proj^T

// ===========================================================================
// Helpers
// ===========================================================================
__device__ __forceinline__ uint32_t smem_to_u32(const void* p) {
    uint32_t a;
    asm("{ .reg .u64 t; cvta.to.shared.u64 t, %1; cvt.u32.u64 %0, t; }"
        : "=r"(a) : "l"(p));
    return a;
}

__device__ __forceinline__ uint32_t f2tf32(float f) {
    uint32_t r;
    asm("cvt.rna.tf32.f32 %0, %1;" : "=r"(r) : "f"(f));
    return r;
}

__device__ __forceinline__ void ldmx4(uint32_t* r, uint32_t addr) {
    asm volatile("ldmatrix.sync.aligned.m8n8.x4.shared.b16 {%0,%1,%2,%3}, [%4];"
                 : "=r"(r[0]), "=r"(r[1]), "=r"(r[2]), "=r"(r[3]) : "r"(addr));
}

__device__ __forceinline__ void mma_tf32(float* c, const uint32_t* a,
                                         const uint32_t* b) {
    asm volatile(
        "mma.sync.aligned.m16n8k8.row.col.f32.tf32.tf32.f32 "
        "{%0,%1,%2,%3}, {%4,%5,%6,%7}, {%8,%9}, {%0,%1,%2,%3};"
        : "+f"(c[0]), "+f"(c[1]), "+f"(c[2]), "+f"(c[3])
        : "r"(a[0]), "r"(a[1]), "r"(a[2]), "r"(a[3]), "r"(b[0]), "r"(b[1]));
}

#define SWZ(off) ((off) ^ (((off) >> 3) & 0x70))

// ===========================================================================
// Weight transpose: out[c][r] = in[r][c]; in is [R][Cc] row-major.
// ===========================================================================
template <int MODE>
__global__ void transpose_kernel(const float* __restrict__ in, int R, int Cc)
{
    __shared__ float t[32][33];
    float* out = (MODE == 0) ? (float*)g_WqkvT : (float*)g_WprojT;
    const int c0 = blockIdx.x * 32, r0 = blockIdx.y * 32;
#pragma unroll
    for (int j = threadIdx.y; j < 32; j += 8)
        t[j][threadIdx.x] = in[(size_t)(r0 + j) * Cc + c0 + threadIdx.x];
    __syncthreads();
#pragma unroll
    for (int j = threadIdx.y; j < 32; j += 8)
        out[(size_t)(c0 + j) * R + r0 + threadIdx.x] = t[threadIdx.x][j];
}

// ===========================================================================
// Tensor-core tf32 GEMM via mma.sync — unchanged from passing R6 kernel.
// ===========================================================================
#define GBK 32
#define GTILE 16384
#define GSMEM (4 * GTILE)

template <int MODE, int N, int K>
__global__ __launch_bounds__(256) void mma_gemm(
    const float* __restrict__ Ap, float* __restrict__ Cp)
{
    extern __shared__ char sm[];
    const uint32_t smem_u32 = smem_to_u32(sm);

    const float* Ag = (MODE == 0) ? Ap : (const float*)g_att;
    const float* Bg = (MODE == 0) ? (const float*)g_WqkvT : (const float*)g_WprojT;
    float* Cg = (MODE == 0) ? (float*)g_qkv : Cp;

    const int tid = threadIdx.x;
    const int lane = tid & 31;
    const int wid = tid >> 5;
    const int warp_m = wid & 1;
    const int warp_n = wid >> 1;
    const int m0 = blockIdx.y * 128;
    const int n0 = blockIdx.x * 128;

    const int frow = tid >> 3;
    const int ff4  = tid & 7;

    float acc[4][4][4];
#pragma unroll
    for (int i = 0; i < 4; i++)
#pragma unroll
        for (int j = 0; j < 4; j++)
#pragma unroll
            for (int k = 0; k < 4; k++) acc[i][j][k] = 0.f;

    const int NCHUNK = K / GBK;

    {
        float4 pa[4], pb[4];
#pragma unroll
        for (int j = 0; j < 4; j++) {
            int row = frow + j * 32;
            pa[j] = *(const float4*)(Ag + (size_t)(m0 + row) * K + ff4 * 4);
            pb[j] = *(const float4*)(Bg + (size_t)(n0 + row) * K + ff4 * 4);
        }
#pragma unroll
        for (int j = 0; j < 4; j++) {
            int row = frow + j * 32;
            uint32_t off = SWZ(row * 128 + ff4 * 16);
            uint4 ta = { f2tf32(pa[j].x), f2tf32(pa[j].y), f2tf32(pa[j].z), f2tf32(pa[j].w) };
            uint4 tb = { f2tf32(pb[j].x), f2tf32(pb[j].y), f2tf32(pb[j].z), f2tf32(pb[j].w) };
            *(uint4*)(sm + off) = ta;
            *(uint4*)(sm + GTILE + off) = tb;
        }
    }
    __syncthreads();

    const int a_row_in_tile = lane & 15;
    const int a_kblk = (lane >> 4) & 1;
    const int b_row_in_pair = ((lane & 16) >> 1) + (lane & 7);
    const int b_kblk = (lane >> 3) & 1;

    for (int i = 0; i < NCHUNK; i++) {
        float4 pa[4], pb[4];
        if (i + 1 < NCHUNK) {
            const int k0 = (i + 1) * GBK;
#pragma unroll
            for (int j = 0; j < 4; j++) {
                int row = frow + j * 32;
                pa[j] = *(const float4*)(Ag + (size_t)(m0 + row) * K + k0 + ff4 * 4);
                pb[j] = *(const float4*)(Bg + (size_t)(n0 + row) * K + k0 + ff4 * 4);
            }
        }

        const uint32_t Abuf = smem_u32 + (uint32_t)(i & 1) * (2 * GTILE);
        const uint32_t Bbuf = Abuf + GTILE;
#pragma unroll
        for (int ks = 0; ks < 4; ks++) {
            uint32_t afr[4][4];
#pragma unroll
            for (int mt = 0; mt < 4; mt++) {
                int row = warp_m * 64 + mt * 16 + a_row_in_tile;
                uint32_t off = SWZ(row * 128 + ks * 32 + a_kblk * 16);
                ldmx4(afr[mt], Abuf + off);
            }
            uint32_t bfr[2][4];
#pragma unroll
            for (int p = 0; p < 2; p++) {
                int row = warp_n * 32 + p * 16 + b_row_in_pair;
                uint32_t off = SWZ(row * 128 + ks * 32 + b_kblk * 16);
                ldmx4(bfr[p], Bbuf + off);
            }
#pragma unroll
            for (int mt = 0; mt < 4; mt++)
#pragma unroll
                for (int nt = 0; nt < 4; nt++)
                    mma_tf32(acc[mt][nt], afr[mt], &bfr[nt >> 1][(nt & 1) * 2]);
        }
        __syncthreads();

        if (i + 1 < NCHUNK) {
            char* dst = sm + (size_t)((i + 1) & 1) * (2 * GTILE);
#pragma unroll
            for (int j = 0; j < 4; j++) {
                int row = frow + j * 32;
                uint32_t off = SWZ(row * 128 + ff4 * 16);
                uint4 ta = { f2tf32(pa[j].x), f2tf32(pa[j].y), f2tf32(pa[j].z), f2tf32(pa[j].w) };
                uint4 tb = { f2tf32(pb[j].x), f2tf32(pb[j].y), f2tf32(pb[j].z), f2tf32(pb[j].w) };
                *(uint4*)(dst + off) = ta;
                *(uint4*)(dst + GTILE + off) = tb;
            }
            __syncthreads();
        }
    }

    const int og = lane >> 2;
    const int ot = lane & 3;
#pragma unroll
    for (int mt = 0; mt < 4; mt++) {
        int r0 = m0 + warp_m * 64 + mt * 16 + og;
#pragma unroll
        for (int nt = 0; nt < 4; nt++) {
            int col = n0 + warp_n * 32 + nt * 8 + ot * 2;
            float2 lo = { acc[mt][nt][0], acc[mt][nt][1] };
            float2 hi = { acc[mt][nt][2], acc[mt][nt][3] };
            *(float2*)(Cg + (size_t)r0 * N + col) = lo;
            *(float2*)(Cg + (size_t)(r0 + 8) * N + col) = hi;
        }
    }
}

// ===========================================================================
// Tensor-core flash attention (tf32 mma.sync, causal).
// Block = (b, h, 128-query tile), 256 thr = 8 warps; warp w owns q rows
// w*16..w*16+15. Key tile = 64. All smem tiles use row stride 68 floats
// (rows advance 4 banks -> conflict-free 8-row LDSM phases).
//   Qs[128][68] : Q rows (k=dim), pre-scaled, tf32
//   Ks[ 64][68] : K rows (n=key, k=dim), tf32
//   Vt[ 64][68] : V transposed (n=dim row, k=key), tf32
//   Ps[128][68] : P rows (k=key), tf32, warp-private rows
// ===========================================================================
#define FSTR 68
#define FLASH2_SMEM_FLOATS (128*FSTR + 64*FSTR + 64*FSTR + 128*FSTR)
#define FLASH2_SMEM_BYTES  (FLASH2_SMEM_FLOATS * 4)   // 104448

__global__ __launch_bounds__(256, 2) void flash_mma_kernel()
{
    extern __shared__ float smf[];
    float* Qs = smf;
    float* Ks = Qs + 128 * FSTR;
    float* Vt = Ks + 64 * FSTR;
    float* Ps = Vt + 64 * FSTR;

    const float* qkv = (const float*)g_qkv;
    float* att = (float*)g_att;

    const uint32_t qs_u32 = smem_to_u32(Qs);
    const uint32_t ks_u32 = smem_to_u32(Ks);
    const uint32_t vt_u32 = smem_to_u32(Vt);
    const uint32_t ps_u32 = smem_to_u32(Ps);

    const int tid = threadIdx.x;
    const int lane = tid & 31;
    const int w = tid >> 5;
    const int h = blockIdx.y;
    const int b = blockIdx.z;
    const int q0 = (gridDim.x - 1 - blockIdx.x) * 128;
    const int base = b * T_ * TC3;
    const int hoff = h * D_;
    const float scale = 0.03125f;          // 1024^-0.5

    // ldmatrix lane-address components
    const int a_row = lane & 15;
    const int a_kb  = (lane >> 4) & 1;
    const int b_row = ((lane & 16) >> 1) + (lane & 7);
    const int b_kb  = (lane >> 3) & 1;
    const int g  = lane >> 2;              // accumulator row group 0..7
    const int t2 = (lane & 3) * 2;         // accumulator col pair

    // Load Q tile [128 x 64] (scaled, tf32)
#pragma unroll
    for (int i = 0; i < 8; i++) {
        int slot = i * 256 + tid;
        int r  = slot >> 4;
        int c4 = (slot & 15) << 2;
        float4 v = *(const float4*)(qkv + base + (size_t)(q0 + r) * TC3 + C_ + hoff + c4);
        uint4 tq = { f2tf32(v.x * scale), f2tf32(v.y * scale),
                     f2tf32(v.z * scale), f2tf32(v.w * scale) };
        *(uint4*)(Qs + r * FSTR + c4) = tq;
    }

    float o[8][4];
#pragma unroll
    for (int nt = 0; nt < 8; nt++)
#pragma unroll
        for (int k = 0; k < 4; k++) o[nt][k] = 0.f;
    float m0 = -1e30f, m1 = -1e30f, l0 = 0.f, l1 = 0.f;

    const int jend = q0 + 128;
    for (int j0 = 0; j0 < jend; j0 += 64) {
        __syncthreads();                   // prior PV / Q-load done before overwrite
        // Load K -> Ks (row-major n=key) and V -> Vt (transposed, row=dim)
#pragma unroll
        for (int i = 0; i < 4; i++) {
            int slot = i * 256 + tid;
            int r  = slot >> 4;            // key row 0..63
            int c4 = (slot & 15) << 2;     // dim 0..60
            const float* gp = qkv + base + (size_t)(j0 + r) * TC3;
            float4 kv = *(const float4*)(gp + hoff + c4);
            uint4 tk = { f2tf32(kv.x), f2tf32(kv.y), f2tf32(kv.z), f2tf32(kv.w) };
            *(uint4*)(Ks + r * FSTR + c4) = tk;
            float4 vv = *(const float4*)(gp + 2 * C_ + hoff + c4);
            ((uint32_t*)Vt)[(c4 + 0) * FSTR + r] = f2tf32(vv.x);
            ((uint32_t*)Vt)[(c4 + 1) * FSTR + r] = f2tf32(vv.y);
            ((uint32_t*)Vt)[(c4 + 2) * FSTR + r] = f2tf32(vv.z);
            ((uint32_t*)Vt)[(c4 + 3) * FSTR + r] = f2tf32(vv.w);
        }
        __syncthreads();

        // S = Q @ K^T : warp computes 16 x 64
        float s[8][4];
#pragma unroll
        for (int nt = 0; nt < 8; nt++)
#pragma unroll
            for (int k = 0; k < 4; k++) s[nt][k] = 0.f;

#pragma unroll
        for (int ks = 0; ks < 8; ks++) {
            uint32_t af[4];
            ldmx4(af, qs_u32 + ((w * 16 + a_row) * FSTR + ks * 8 + a_kb * 4) * 4);
            uint32_t bf[4][4];
#pragma unroll
            for (int p = 0; p < 4; p++)
                ldmx4(bf[p], ks_u32 + ((p * 16 + b_row) * FSTR + ks * 8 + b_kb * 4) * 4);
#pragma unroll
            for (int nt = 0; nt < 8; nt++)
                mma_tf32(s[nt], af, &bf[nt >> 1][(nt & 1) * 2]);
        }

        // Causal mask (only diagonal-intersecting tiles)
        if (j0 + 64 > q0) {
            const int q_lo = q0 + w * 16 + g;
            const int q_hi = q_lo + 8;
#pragma unroll
            for (int nt = 0; nt < 8; nt++) {
                int j = j0 + nt * 8 + t2;
                if (j     > q_lo) s[nt][0] = -1e30f;
                if (j + 1 > q_lo) s[nt][1] = -1e30f;
                if (j     > q_hi) s[nt][2] = -1e30f;
                if (j + 1 > q_hi) s[nt][3] = -1e30f;
            }
        }

        // Online softmax on the two rows this thread owns (g and g+8)
        float mx0 = -1e30f, mx1 = -1e30f;
#pragma unroll
        for (int nt = 0; nt < 8; nt++) {
            mx0 = fmaxf(mx0, fmaxf(s[nt][0], s[nt][1]));
            mx1 = fmaxf(mx1, fmaxf(s[nt][2], s[nt][3]));
        }
        mx0 = fmaxf(mx0, __shfl_xor_sync(0xffffffffu, mx0, 1));
        mx0 = fmaxf(mx0, __shfl_xor_sync(0xffffffffu, mx0, 2));
        mx1 = fmaxf(mx1, __shfl_xor_sync(0xffffffffu, mx1, 1));
        mx1 = fmaxf(mx1, __shfl_xor_sync(0xffffffffu, mx1, 2));
        const float mn0 = fmaxf(m0, mx0), mn1 = fmaxf(m1, mx1);
        const float al0 = __expf(m0 - mn0), al1 = __expf(m1 - mn1);
        m0 = mn0; m1 = mn1;

        float rs0 = 0.f, rs1 = 0.f;
        uint32_t* PsRow0 = (uint32_t*)Ps + (w * 16 + g) * FSTR;
        uint32_t* PsRow1 = PsRow0 + 8 * FSTR;
#pragma unroll
        for (int nt = 0; nt < 8; nt++) {
            float p00 = __expf(s[nt][0] - mn0);
            float p01 = __expf(s[nt][1] - mn0);
            float p10 = __expf(s[nt][2] - mn1);
            float p11 = __expf(s[nt][3] - mn1);
            rs0 += p00 + p01;
            rs1 += p10 + p11;
            uint2 w0 = { f2tf32(p00), f2tf32(p01) };
            uint2 w1 = { f2tf32(p10), f2tf32(p11) };
            *(uint2*)(PsRow0 + nt * 8 + t2) = w0;
            *(uint2*)(PsRow1 + nt * 8 + t2) = w1;
        }
        rs0 += __shfl_xor_sync(0xffffffffu, rs0, 1);
        rs0 += __shfl_xor_sync(0xffffffffu, rs0, 2);
        rs1 += __shfl_xor_sync(0xffffffffu, rs1, 1);
        rs1 += __shfl_xor_sync(0xffffffffu, rs1, 2);
        l0 = l0 * al0 + rs0;
        l1 = l1 * al1 + rs1;
#pragma unroll
        for (int nt = 0; nt < 8; nt++) {
            o[nt][0] *= al0; o[nt][1] *= al0;
            o[nt][2] *= al1; o[nt][3] *= al1;
        }
        __syncwarp();                       // Ps rows are warp-private

        // O += P @ V : A = Ps (k=key), B = Vt (n=dim, k=key)
#pragma unroll
        for (int ks = 0; ks < 8; ks++) {
            uint32_t af[4];
            ldmx4(af, ps_u32 + ((w * 16 + a_row) * FSTR + ks * 8 + a_kb * 4) * 4);
            uint32_t bf[4][4];
#pragma unroll
            for (int p = 0; p < 4; p++)
                ldmx4(bf[p], vt_u32 + ((p * 16 + b_row) * FSTR + ks * 8 + b_kb * 4) * 4);
#pragma unroll
            for (int nt = 0; nt < 8; nt++)
                mma_tf32(o[nt], af, &bf[nt >> 1][(nt & 1) * 2]);
        }
    }

    // Epilogue: normalize and store
    const float inv0 = 1.f / l0, inv1 = 1.f / l1;
    const int q_lo = q0 + w * 16 + g;
    float* arow0 = att + (size_t)(b * T_ + q_lo) * C_ + hoff;
    float* arow1 = arow0 + (size_t)8 * C_;
#pragma unroll
    for (int nt = 0; nt < 8; nt++) {
        float2 lo = { o[nt][0] * inv0, o[nt][1] * inv0 };
        float2 hi = { o[nt][2] * inv1, o[nt][3] * inv1 };
        *(float2*)(arow0 + nt * 8 + t2) = lo;
        *(float2*)(arow1 + nt * 8 + t2) = hi;
    }
}

// ===========================================================================
// Launch
// ===========================================================================
extern "C" void kernel_launch(void* const* d_in, const int* in_sizes, int n_in,
                              void* d_out, int out_size)
{
    const float* x     = (const float*)d_in[0];   // [B,T,C]
    const float* Wqkv  = (const float*)d_in[1];   // [C,3C]
    const float* Wproj = (const float*)d_in[2];   // [C,C]
    float* out = (float*)d_out;                   // [B,T,C]

    cudaFuncSetAttribute(flash_mma_kernel,
                         cudaFuncAttributeMaxDynamicSharedMemorySize,
                         FLASH2_SMEM_BYTES);
    cudaFuncSetAttribute(mma_gemm<0, TC3, C_>,
                         cudaFuncAttributeMaxDynamicSharedMemorySize, GSMEM);
    cudaFuncSetAttribute(mma_gemm<1, C_, C_>,
                         cudaFuncAttributeMaxDynamicSharedMemorySize, GSMEM);

    // 0) Transpose weights -> K-major B operands
    transpose_kernel<0><<<dim3(TC3 / 32, C_ / 32), dim3(32, 8)>>>(Wqkv, C_, TC3);
    transpose_kernel<1><<<dim3(C_ / 32, C_ / 32), dim3(32, 8)>>>(Wproj, C_, C_);

    // 1) g_qkv = x @ W_qkv   (tf32 mma.sync)
    mma_gemm<0, TC3, C_><<<dim3(TC3 / 128, (B_ * T_) / 128), 256, GSMEM>>>(x, nullptr);

    // 2) tensor-core flash attention: g_qkv -> g_att
    flash_mma_kernel<<<dim3(T_ / 128, H_, B_), 256, FLASH2_SMEM_BYTES>>>();

    // 3) out = g_att @ W_proj  (tf32 mma.sync)
    mma_gemm<1, C_, C_><<<dim3(C_ / 128, (B_ * T_) / 128), 256, GSMEM>>>(nullptr, out);
}

// round 11
// speedup vs baseline: 3.5537x; 1.1681x over previous
#include <cuda_runtime.h>
#include <cstdint>

// Problem constants
#define B_   4
#define T_   2048
#define C_   1024
#define H_   16
#define D_   64
#define TC3  (3 * C_)

// Scratch (allocation-free rule: __device__ globals)
__device__ float g_qkv[B_ * T_ * TC3];     // [B,T,3C]  k|q|v
__device__ float g_att[B_ * T_ * C_];      // [B,T,C]  (tf32-rounded by flash epilogue)
__device__ float g_xr[B_ * T_ * C_];       // [B,T,C]  x pre-rounded to tf32
__device__ float g_WqkvT[TC3 * C_];        // [3C, C]  = W_qkv^T (K-major, tf32-rounded)
__device__ float g_WprojT[C_ * C_];        // [C, C]   = W_proj^T (tf32-rounded)

// ===========================================================================
// Helpers
// ===========================================================================
__device__ __forceinline__ uint32_t smem_to_u32(const void* p) {
    uint32_t a;
    asm("{ .reg .u64 t; cvta.to.shared.u64 t, %1; cvt.u32.u64 %0, t; }"
        : "=r"(a) : "l"(p));
    return a;
}

__device__ __forceinline__ uint32_t f2tf32(float f) {
    uint32_t r;
    asm("cvt.rna.tf32.f32 %0, %1;" : "=r"(r) : "f"(f));
    return r;
}

__device__ __forceinline__ void ldmx4(uint32_t* r, uint32_t addr) {
    asm volatile("ldmatrix.sync.aligned.m8n8.x4.shared.b16 {%0,%1,%2,%3}, [%4];"
                 : "=r"(r[0]), "=r"(r[1]), "=r"(r[2]), "=r"(r[3]) : "r"(addr));
}

__device__ __forceinline__ void mma_tf32(float* c, const uint32_t* a,
                                         const uint32_t* b) {
    asm volatile(
        "mma.sync.aligned.m16n8k8.row.col.f32.tf32.tf32.f32 "
        "{%0,%1,%2,%3}, {%4,%5,%6,%7}, {%8,%9}, {%0,%1,%2,%3};"
        : "+f"(c[0]), "+f"(c[1]), "+f"(c[2]), "+f"(c[3])
        : "r"(a[0]), "r"(a[1]), "r"(a[2]), "r"(a[3]), "r"(b[0]), "r"(b[1]));
}

__device__ __forceinline__ void cp_async16(uint32_t smem_dst, const void* gsrc) {
    asm volatile("cp.async.cg.shared.global [%0], [%1], 16;"
                 :: "r"(smem_dst), "l"(gsrc));
}
#define CP_COMMIT() asm volatile("cp.async.commit_group;" ::: "memory")
#define CP_WAIT1()  asm volatile("cp.async.wait_group 1;" ::: "memory")

#define SWZ(off) ((off) ^ (((off) >> 3) & 0x70))

// ===========================================================================
// Pre-round x to tf32 (RNA) -> g_xr
// ===========================================================================
__global__ void round_x_kernel(const float* __restrict__ x)
{
    const int n4 = (B_ * T_ * C_) / 4;
    for (int i = blockIdx.x * blockDim.x + threadIdx.x; i < n4;
         i += gridDim.x * blockDim.x) {
        float4 v = ((const float4*)x)[i];
        uint4 t = { f2tf32(v.x), f2tf32(v.y), f2tf32(v.z), f2tf32(v.w) };
        ((uint4*)g_xr)[i] = t;
    }
}

// ===========================================================================
// Weight transpose + tf32 round: out[c][r] = tf32(in[r][c]).
// ===========================================================================
template <int MODE>
__global__ void transpose_kernel(const float* __restrict__ in, int R, int Cc)
{
    __shared__ float t[32][33];
    float* out = (MODE == 0) ? (float*)g_WqkvT : (float*)g_WprojT;
    const int c0 = blockIdx.x * 32, r0 = blockIdx.y * 32;
#pragma unroll
    for (int j = threadIdx.y; j < 32; j += 8)
        t[j][threadIdx.x] = in[(size_t)(r0 + j) * Cc + c0 + threadIdx.x];
    __syncthreads();
#pragma unroll
    for (int j = threadIdx.y; j < 32; j += 8)
        out[(size_t)(c0 + j) * R + r0 + threadIdx.x] =
            __uint_as_float(f2tf32(t[threadIdx.x][j]));
}

// ===========================================================================
// Tensor-core tf32 GEMM, cp.async 3-stage pipeline.
// C[M,N] = A[M,K] @ Bt[N,K]^T, operands pre-rounded tf32 in gmem.
// CTA 128x128, BK=32 (128B rows, SW128), 256 thr = 8 warps (2M x 4N).
// MODE 0: A = g_xr,  Bt = g_WqkvT, C = g_qkv
// MODE 1: A = g_att, Bt = g_WprojT, C = param (out)
// ===========================================================================
#define G2_STAGES 3
#define G2_TILE   16384                   // 128 rows x 128 bytes
#define G2_STAGE_BYTES (2 * G2_TILE)      // A + B
#define G2_SMEM   (G2_STAGES * G2_STAGE_BYTES)   // 98304

template <int K>
__device__ __forceinline__ void g2_issue(
    const float* __restrict__ Ag, const float* __restrict__ Bg,
    uint32_t Abuf, uint32_t Bbuf, int m0, int n0, int k0, int tid)
{
#pragma unroll
    for (int j = 0; j < 4; j++) {
        int slot = tid + j * 256;          // 0..1023
        int row = slot >> 3;               // 0..127
        int f4  = slot & 7;                // 16B chunk
        uint32_t off = SWZ(row * 128 + f4 * 16);
        cp_async16(Abuf + off, Ag + (size_t)(m0 + row) * K + k0 + f4 * 4);
        cp_async16(Bbuf + off, Bg + (size_t)(n0 + row) * K + k0 + f4 * 4);
    }
}

template <int MODE, int N, int K>
__global__ __launch_bounds__(256, 2) void mma_gemm2(float* __restrict__ Cp)
{
    extern __shared__ char sm[];
    const uint32_t smem_u32 = smem_to_u32(sm);

    const float* Ag = (MODE == 0) ? (const float*)g_xr : (const float*)g_att;
    const float* Bg = (MODE == 0) ? (const float*)g_WqkvT : (const float*)g_WprojT;
    float* Cg = (MODE == 0) ? (float*)g_qkv : Cp;

    const int tid = threadIdx.x;
    const int lane = tid & 31;
    const int wid = tid >> 5;
    const int warp_m = wid & 1;
    const int warp_n = wid >> 1;
    const int m0 = blockIdx.y * 128;
    const int n0 = blockIdx.x * 128;

    float acc[4][4][4];
#pragma unroll
    for (int i = 0; i < 4; i++)
#pragma unroll
        for (int j = 0; j < 4; j++)
#pragma unroll
            for (int k = 0; k < 4; k++) acc[i][j][k] = 0.f;

    const int NCHUNK = K / 32;

    // Prologue: stages 0,1 in flight
    g2_issue<K>(Ag, Bg, smem_u32, smem_u32 + G2_TILE, m0, n0, 0, tid);
    CP_COMMIT();
    g2_issue<K>(Ag, Bg, smem_u32 + G2_STAGE_BYTES,
                smem_u32 + G2_STAGE_BYTES + G2_TILE, m0, n0, 32, tid);
    CP_COMMIT();

    const int a_row_in_tile = lane & 15;
    const int a_kblk = (lane >> 4) & 1;
    const int b_row_in_pair = ((lane & 16) >> 1) + (lane & 7);
    const int b_kblk = (lane >> 3) & 1;

    int st = 0;                            // stage index of chunk i
    for (int i = 0; i < NCHUNK; i++) {
        CP_WAIT1();                        // chunk i resident
        __syncthreads();

        // Issue chunk i+2 into the free stage (the one chunk i-1 used)
        if (i + 2 < NCHUNK) {
            int sn = st + 2; if (sn >= G2_STAGES) sn -= G2_STAGES;
            uint32_t base = smem_u32 + (uint32_t)sn * G2_STAGE_BYTES;
            g2_issue<K>(Ag, Bg, base, base + G2_TILE, m0, n0, (i + 2) * 32, tid);
        }
        CP_COMMIT();

        const uint32_t Abuf = smem_u32 + (uint32_t)st * G2_STAGE_BYTES;
        const uint32_t Bbuf = Abuf + G2_TILE;
#pragma unroll
        for (int ks = 0; ks < 4; ks++) {
            uint32_t afr[4][4];
#pragma unroll
            for (int mt = 0; mt < 4; mt++) {
                int row = warp_m * 64 + mt * 16 + a_row_in_tile;
                ldmx4(afr[mt], Abuf + SWZ(row * 128 + ks * 32 + a_kblk * 16));
            }
            uint32_t bfr[2][4];
#pragma unroll
            for (int p = 0; p < 2; p++) {
                int row = warp_n * 32 + p * 16 + b_row_in_pair;
                ldmx4(bfr[p], Bbuf + SWZ(row * 128 + ks * 32 + b_kblk * 16));
            }
#pragma unroll
            for (int mt = 0; mt < 4; mt++)
#pragma unroll
                for (int nt = 0; nt < 4; nt++)
                    mma_tf32(acc[mt][nt], afr[mt], &bfr[nt >> 1][(nt & 1) * 2]);
        }

        if (++st == G2_STAGES) st = 0;
    }

    const int og = lane >> 2;
    const int ot = lane & 3;
#pragma unroll
    for (int mt = 0; mt < 4; mt++) {
        int r0 = m0 + warp_m * 64 + mt * 16 + og;
#pragma unroll
        for (int nt = 0; nt < 4; nt++) {
            int col = n0 + warp_n * 32 + nt * 8 + ot * 2;
            float2 lo = { acc[mt][nt][0], acc[mt][nt][1] };
            float2 hi = { acc[mt][nt][2], acc[mt][nt][3] };
            *(float2*)(Cg + (size_t)r0 * N + col) = lo;
            *(float2*)(Cg + (size_t)(r0 + 8) * N + col) = hi;
        }
    }
}

// ===========================================================================
// Tensor-core flash attention (tf32 mma.sync, causal) — body unchanged from
// the passing R10 kernel; epilogue now rounds g_att to tf32 (RNA) so the
// proj GEMM can cp.async it raw.
// ===========================================================================
#define FSTR 68
#define FLASH2_SMEM_FLOATS (128*FSTR + 64*FSTR + 64*FSTR + 128*FSTR)
#define FLASH2_SMEM_BYTES  (FLASH2_SMEM_FLOATS * 4)   // 104448

__global__ __launch_bounds__(256, 2) void flash_mma_kernel()
{
    extern __shared__ float smf[];
    float* Qs = smf;
    float* Ks = Qs + 128 * FSTR;
    float* Vt = Ks + 64 * FSTR;
    float* Ps = Vt + 64 * FSTR;

    const float* qkv = (const float*)g_qkv;
    float* att = (float*)g_att;

    const uint32_t qs_u32 = smem_to_u32(Qs);
    const uint32_t ks_u32 = smem_to_u32(Ks);
    const uint32_t vt_u32 = smem_to_u32(Vt);
    const uint32_t ps_u32 = smem_to_u32(Ps);

    const int tid = threadIdx.x;
    const int lane = tid & 31;
    const int w = tid >> 5;
    const int h = blockIdx.y;
    const int b = blockIdx.z;
    const int q0 = (gridDim.x - 1 - blockIdx.x) * 128;
    const int base = b * T_ * TC3;
    const int hoff = h * D_;
    const float scale = 0.03125f;          // 1024^-0.5

    const int a_row = lane & 15;
    const int a_kb  = (lane >> 4) & 1;
    const int b_row = ((lane & 16) >> 1) + (lane & 7);
    const int b_kb  = (lane >> 3) & 1;
    const int g  = lane >> 2;
    const int t2 = (lane & 3) * 2;

#pragma unroll
    for (int i = 0; i < 8; i++) {
        int slot = i * 256 + tid;
        int r  = slot >> 4;
        int c4 = (slot & 15) << 2;
        float4 v = *(const float4*)(qkv + base + (size_t)(q0 + r) * TC3 + C_ + hoff + c4);
        uint4 tq = { f2tf32(v.x * scale), f2tf32(v.y * scale),
                     f2tf32(v.z * scale), f2tf32(v.w * scale) };
        *(uint4*)(Qs + r * FSTR + c4) = tq;
    }

    float o[8][4];
#pragma unroll
    for (int nt = 0; nt < 8; nt++)
#pragma unroll
        for (int k = 0; k < 4; k++) o[nt][k] = 0.f;
    float m0 = -1e30f, m1 = -1e30f, l0 = 0.f, l1 = 0.f;

    const int jend = q0 + 128;
    for (int j0 = 0; j0 < jend; j0 += 64) {
        __syncthreads();
#pragma unroll
        for (int i = 0; i < 4; i++) {
            int slot = i * 256 + tid;
            int r  = slot >> 4;
            int c4 = (slot & 15) << 2;
            const float* gp = qkv + base + (size_t)(j0 + r) * TC3;
            float4 kv = *(const float4*)(gp + hoff + c4);
            uint4 tk = { f2tf32(kv.x), f2tf32(kv.y), f2tf32(kv.z), f2tf32(kv.w) };
            *(uint4*)(Ks + r * FSTR + c4) = tk;
            float4 vv = *(const float4*)(gp + 2 * C_ + hoff + c4);
            ((uint32_t*)Vt)[(c4 + 0) * FSTR + r] = f2tf32(vv.x);
            ((uint32_t*)Vt)[(c4 + 1) * FSTR + r] = f2tf32(vv.y);
            ((uint32_t*)Vt)[(c4 + 2) * FSTR + r] = f2tf32(vv.z);
            ((uint32_t*)Vt)[(c4 + 3) * FSTR + r] = f2tf32(vv.w);
        }
        __syncthreads();

        float s[8][4];
#pragma unroll
        for (int nt = 0; nt < 8; nt++)
#pragma unroll
            for (int k = 0; k < 4; k++) s[nt][k] = 0.f;

#pragma unroll
        for (int ks = 0; ks < 8; ks++) {
            uint32_t af[4];
            ldmx4(af, qs_u32 + ((w * 16 + a_row) * FSTR + ks * 8 + a_kb * 4) * 4);
            uint32_t bf[4][4];
#pragma unroll
            for (int p = 0; p < 4; p++)
                ldmx4(bf[p], ks_u32 + ((p * 16 + b_row) * FSTR + ks * 8 + b_kb * 4) * 4);
#pragma unroll
            for (int nt = 0; nt < 8; nt++)
                mma_tf32(s[nt], af, &bf[nt >> 1][(nt & 1) * 2]);
        }

        if (j0 + 64 > q0) {
            const int q_lo = q0 + w * 16 + g;
            const int q_hi = q_lo + 8;
#pragma unroll
            for (int nt = 0; nt < 8; nt++) {
                int j = j0 + nt * 8 + t2;
                if (j     > q_lo) s[nt][0] = -1e30f;
                if (j + 1 > q_lo) s[nt][1] = -1e30f;
                if (j     > q_hi) s[nt][2] = -1e30f;
                if (j + 1 > q_hi) s[nt][3] = -1e30f;
            }
        }

        float mx0 = -1e30f, mx1 = -1e30f;
#pragma unroll
        for (int nt = 0; nt < 8; nt++) {
            mx0 = fmaxf(mx0, fmaxf(s[nt][0], s[nt][1]));
            mx1 = fmaxf(mx1, fmaxf(s[nt][2], s[nt][3]));
        }
        mx0 = fmaxf(mx0, __shfl_xor_sync(0xffffffffu, mx0, 1));
        mx0 = fmaxf(mx0, __shfl_xor_sync(0xffffffffu, mx0, 2));
        mx1 = fmaxf(mx1, __shfl_xor_sync(0xffffffffu, mx1, 1));
        mx1 = fmaxf(mx1, __shfl_xor_sync(0xffffffffu, mx1, 2));
        const float mn0 = fmaxf(m0, mx0), mn1 = fmaxf(m1, mx1);
        const float al0 = __expf(m0 - mn0), al1 = __expf(m1 - mn1);
        m0 = mn0; m1 = mn1;

        float rs0 = 0.f, rs1 = 0.f;
        uint32_t* PsRow0 = (uint32_t*)Ps + (w * 16 + g) * FSTR;
        uint32_t* PsRow1 = PsRow0 + 8 * FSTR;
#pragma unroll
        for (int nt = 0; nt < 8; nt++) {
            float p00 = __expf(s[nt][0] - mn0);
            float p01 = __expf(s[nt][1] - mn0);
            float p10 = __expf(s[nt][2] - mn1);
            float p11 = __expf(s[nt][3] - mn1);
            rs0 += p00 + p01;
            rs1 += p10 + p11;
            uint2 w0 = { f2tf32(p00), f2tf32(p01) };
            uint2 w1 = { f2tf32(p10), f2tf32(p11) };
            *(uint2*)(PsRow0 + nt * 8 + t2) = w0;
            *(uint2*)(PsRow1 + nt * 8 + t2) = w1;
        }
        rs0 += __shfl_xor_sync(0xffffffffu, rs0, 1);
        rs0 += __shfl_xor_sync(0xffffffffu, rs0, 2);
        rs1 += __shfl_xor_sync(0xffffffffu, rs1, 1);
        rs1 += __shfl_xor_sync(0xffffffffu, rs1, 2);
        l0 = l0 * al0 + rs0;
        l1 = l1 * al1 + rs1;
#pragma unroll
        for (int nt = 0; nt < 8; nt++) {
            o[nt][0] *= al0; o[nt][1] *= al0;
            o[nt][2] *= al1; o[nt][3] *= al1;
        }
        __syncwarp();

#pragma unroll
        for (int ks = 0; ks < 8; ks++) {
            uint32_t af[4];
            ldmx4(af, ps_u32 + ((w * 16 + a_row) * FSTR + ks * 8 + a_kb * 4) * 4);
            uint32_t bf[4][4];
#pragma unroll
            for (int p = 0; p < 4; p++)
                ldmx4(bf[p], vt_u32 + ((p * 16 + b_row) * FSTR + ks * 8 + b_kb * 4) * 4);
#pragma unroll
            for (int nt = 0; nt < 8; nt++)
                mma_tf32(o[nt], af, &bf[nt >> 1][(nt & 1) * 2]);
        }
    }

    // Epilogue: normalize, round to tf32 (RNA), store
    const float inv0 = 1.f / l0, inv1 = 1.f / l1;
    const int q_lo = q0 + w * 16 + g;
    float* arow0 = att + (size_t)(b * T_ + q_lo) * C_ + hoff;
    float* arow1 = arow0 + (size_t)8 * C_;
#pragma unroll
    for (int nt = 0; nt < 8; nt++) {
        float2 lo = { __uint_as_float(f2tf32(o[nt][0] * inv0)),
                      __uint_as_float(f2tf32(o[nt][1] * inv0)) };
        float2 hi = { __uint_as_float(f2tf32(o[nt][2] * inv1)),
                      __uint_as_float(f2tf32(o[nt][3] * inv1)) };
        *(float2*)(arow0 + nt * 8 + t2) = lo;
        *(float2*)(arow1 + nt * 8 + t2) = hi;
    }
}

// ===========================================================================
// Launch
// ===========================================================================
extern "C" void kernel_launch(void* const* d_in, const int* in_sizes, int n_in,
                              void* d_out, int out_size)
{
    const float* x     = (const float*)d_in[0];   // [B,T,C]
    const float* Wqkv  = (const float*)d_in[1];   // [C,3C]
    const float* Wproj = (const float*)d_in[2];   // [C,C]
    float* out = (float*)d_out;                   // [B,T,C]

    cudaFuncSetAttribute(flash_mma_kernel,
                         cudaFuncAttributeMaxDynamicSharedMemorySize,
                         FLASH2_SMEM_BYTES);
    cudaFuncSetAttribute(mma_gemm2<0, TC3, C_>,
                         cudaFuncAttributeMaxDynamicSharedMemorySize, G2_SMEM);
    cudaFuncSetAttribute(mma_gemm2<1, C_, C_>,
                         cudaFuncAttributeMaxDynamicSharedMemorySize, G2_SMEM);

    // 0) Pre-round x; transpose+round weights
    round_x_kernel<<<512, 256>>>(x);
    transpose_kernel<0><<<dim3(TC3 / 32, C_ / 32), dim3(32, 8)>>>(Wqkv, C_, TC3);
    transpose_kernel<1><<<dim3(C_ / 32, C_ / 32), dim3(32, 8)>>>(Wproj, C_, C_);

    // 1) g_qkv = x @ W_qkv   (tf32 mma.sync, cp.async pipeline)
    mma_gemm2<0, TC3, C_><<<dim3(TC3 / 128, (B_ * T_) / 128), 256, G2_SMEM>>>(nullptr);

    // 2) tensor-core flash attention: g_qkv -> g_att (tf32-rounded)
    flash_mma_kernel<<<dim3(T_ / 128, H_, B_), 256, FLASH2_SMEM_BYTES>>>();

    // 3) out = g_att @ W_proj  (tf32 mma.sync, cp.async pipeline)
    mma_gemm2<1, C_, C_><<<dim3(C_ / 128, (B_ * T_) / 128), 256, G2_SMEM>>>(out);
}

// round 12
// speedup vs baseline: 4.1595x; 1.1705x over previous
#include <cuda_runtime.h>
#include <cstdint>

// Problem constants
#define B_   4
#define T_   2048
#define C_   1024
#define H_   16
#define D_   64
#define TC3  (3 * C_)

// Scratch (allocation-free rule: __device__ globals)
__device__ float g_qkv[B_ * T_ * TC3];     // [B,T,3C]  k|q (v unused), tf32-rounded, q pre-scaled
__device__ float g_vT[B_ * C_ * T_];       // [B][H*D][T]  V transposed, tf32-rounded
__device__ float g_att[B_ * T_ * C_];      // [B,T,C]  tf32-rounded by flash epilogue
__device__ float g_xr[B_ * T_ * C_];       // [B,T,C]  x pre-rounded to tf32
__device__ float g_WqkvT[TC3 * C_];        // [3C, C] = W_qkv^T, tf32-rounded, q-rows pre-scaled
__device__ float g_WprojT[C_ * C_];        // [C, C]  = W_proj^T, tf32-rounded

// ===========================================================================
// Helpers
// ===========================================================================
__device__ __forceinline__ uint32_t smem_to_u32(const void* p) {
    uint32_t a;
    asm("{ .reg .u64 t; cvta.to.shared.u64 t, %1; cvt.u32.u64 %0, t; }"
        : "=r"(a) : "l"(p));
    return a;
}

__device__ __forceinline__ uint32_t f2tf32(float f) {
    uint32_t r;
    asm("cvt.rna.tf32.f32 %0, %1;" : "=r"(r) : "f"(f));
    return r;
}

__device__ __forceinline__ void ldmx4(uint32_t* r, uint32_t addr) {
    asm volatile("ldmatrix.sync.aligned.m8n8.x4.shared.b16 {%0,%1,%2,%3}, [%4];"
                 : "=r"(r[0]), "=r"(r[1]), "=r"(r[2]), "=r"(r[3]) : "r"(addr));
}

__device__ __forceinline__ void mma_tf32(float* c, const uint32_t* a,
                                         const uint32_t* b) {
    asm volatile(
        "mma.sync.aligned.m16n8k8.row.col.f32.tf32.tf32.f32 "
        "{%0,%1,%2,%3}, {%4,%5,%6,%7}, {%8,%9}, {%0,%1,%2,%3};"
        : "+f"(c[0]), "+f"(c[1]), "+f"(c[2]), "+f"(c[3])
        : "r"(a[0]), "r"(a[1]), "r"(a[2]), "r"(a[3]), "r"(b[0]), "r"(b[1]));
}

__device__ __forceinline__ void cp_async16(uint32_t smem_dst, const void* gsrc) {
    asm volatile("cp.async.cg.shared.global [%0], [%1], 16;"
                 :: "r"(smem_dst), "l"(gsrc));
}
#define CP_COMMIT() asm volatile("cp.async.commit_group;" ::: "memory")
#define CP_WAIT1()  asm volatile("cp.async.wait_group 1;" ::: "memory")
#define CP_WAIT0()  asm volatile("cp.async.wait_group 0;" ::: "memory")

#define SWZ(off) ((off) ^ (((off) >> 3) & 0x70))

// ===========================================================================
// Pre-round x to tf32 (RNA) -> g_xr
// ===========================================================================
__global__ void round_x_kernel(const float* __restrict__ x)
{
    const int n4 = (B_ * T_ * C_) / 4;
    for (int i = blockIdx.x * blockDim.x + threadIdx.x; i < n4;
         i += gridDim.x * blockDim.x) {
        float4 v = ((const float4*)x)[i];
        uint4 t = { f2tf32(v.x), f2tf32(v.y), f2tf32(v.z), f2tf32(v.w) };
        ((uint4*)g_xr)[i] = t;
    }
}

// ===========================================================================
// Weight transpose + tf32 round. MODE 0 also scales q-rows (out rows C..2C-1)
// by 2^-5 (exact) so Q comes out of the QKV GEMM pre-scaled.
// ===========================================================================
template <int MODE>
__global__ void transpose_kernel(const float* __restrict__ in, int R, int Cc)
{
    __shared__ float t[32][33];
    float* out = (MODE == 0) ? (float*)g_WqkvT : (float*)g_WprojT;
    const int c0 = blockIdx.x * 32, r0 = blockIdx.y * 32;
#pragma unroll
    for (int j = threadIdx.y; j < 32; j += 8)
        t[j][threadIdx.x] = in[(size_t)(r0 + j) * Cc + c0 + threadIdx.x];
    __syncthreads();
#pragma unroll
    for (int j = threadIdx.y; j < 32; j += 8) {
        int orow = c0 + j;
        float v = t[threadIdx.x][j];
        if (MODE == 0 && orow >= C_ && orow < 2 * C_) v *= 0.03125f;
        out[(size_t)orow * R + r0 + threadIdx.x] = __uint_as_float(f2tf32(v));
    }
}

// ===========================================================================
// Tensor-core tf32 GEMM, cp.async 3-stage pipeline.
// MODE 0: A = g_xr, Bt = g_WqkvT; k,q -> g_qkv (tf32-rounded);
//         v -> g_vT transposed (tf32-rounded).
// MODE 1: A = g_att, Bt = g_WprojT, C = param out (full fp32).
// ===========================================================================
#define G2_STAGES 3
#define G2_TILE   16384
#define G2_STAGE_BYTES (2 * G2_TILE)
#define G2_SMEM   (G2_STAGES * G2_STAGE_BYTES)   // 98304

template <int K>
__device__ __forceinline__ void g2_issue(
    const float* __restrict__ Ag, const float* __restrict__ Bg,
    uint32_t Abuf, uint32_t Bbuf, int m0, int n0, int k0, int tid)
{
#pragma unroll
    for (int j = 0; j < 4; j++) {
        int slot = tid + j * 256;
        int row = slot >> 3;
        int f4  = slot & 7;
        uint32_t off = SWZ(row * 128 + f4 * 16);
        cp_async16(Abuf + off, Ag + (size_t)(m0 + row) * K + k0 + f4 * 4);
        cp_async16(Bbuf + off, Bg + (size_t)(n0 + row) * K + k0 + f4 * 4);
    }
}

template <int MODE, int N, int K>
__global__ __launch_bounds__(256, 2) void mma_gemm2(float* __restrict__ Cp)
{
    extern __shared__ char sm[];
    const uint32_t smem_u32 = smem_to_u32(sm);

    const float* Ag = (MODE == 0) ? (const float*)g_xr : (const float*)g_att;
    const float* Bg = (MODE == 0) ? (const float*)g_WqkvT : (const float*)g_WprojT;

    const int tid = threadIdx.x;
    const int lane = tid & 31;
    const int wid = tid >> 5;
    const int warp_m = wid & 1;
    const int warp_n = wid >> 1;
    const int m0 = blockIdx.y * 128;
    const int n0 = blockIdx.x * 128;

    float acc[4][4][4];
#pragma unroll
    for (int i = 0; i < 4; i++)
#pragma unroll
        for (int j = 0; j < 4; j++)
#pragma unroll
            for (int k = 0; k < 4; k++) acc[i][j][k] = 0.f;

    const int NCHUNK = K / 32;

    g2_issue<K>(Ag, Bg, smem_u32, smem_u32 + G2_TILE, m0, n0, 0, tid);
    CP_COMMIT();
    g2_issue<K>(Ag, Bg, smem_u32 + G2_STAGE_BYTES,
                smem_u32 + G2_STAGE_BYTES + G2_TILE, m0, n0, 32, tid);
    CP_COMMIT();

    const int a_row_in_tile = lane & 15;
    const int a_kblk = (lane >> 4) & 1;
    const int b_row_in_pair = ((lane & 16) >> 1) + (lane & 7);
    const int b_kblk = (lane >> 3) & 1;

    int st = 0;
    for (int i = 0; i < NCHUNK; i++) {
        CP_WAIT1();
        __syncthreads();

        if (i + 2 < NCHUNK) {
            int sn = st + 2; if (sn >= G2_STAGES) sn -= G2_STAGES;
            uint32_t base = smem_u32 + (uint32_t)sn * G2_STAGE_BYTES;
            g2_issue<K>(Ag, Bg, base, base + G2_TILE, m0, n0, (i + 2) * 32, tid);
        }
        CP_COMMIT();

        const uint32_t Abuf = smem_u32 + (uint32_t)st * G2_STAGE_BYTES;
        const uint32_t Bbuf = Abuf + G2_TILE;
#pragma unroll
        for (int ks = 0; ks < 4; ks++) {
            uint32_t afr[4][4];
#pragma unroll
            for (int mt = 0; mt < 4; mt++) {
                int row = warp_m * 64 + mt * 16 + a_row_in_tile;
                ldmx4(afr[mt], Abuf + SWZ(row * 128 + ks * 32 + a_kblk * 16));
            }
            uint32_t bfr[2][4];
#pragma unroll
            for (int p = 0; p < 2; p++) {
                int row = warp_n * 32 + p * 16 + b_row_in_pair;
                ldmx4(bfr[p], Bbuf + SWZ(row * 128 + ks * 32 + b_kblk * 16));
            }
#pragma unroll
            for (int mt = 0; mt < 4; mt++)
#pragma unroll
                for (int nt = 0; nt < 4; nt++)
                    mma_tf32(acc[mt][nt], afr[mt], &bfr[nt >> 1][(nt & 1) * 2]);
        }

        if (++st == G2_STAGES) st = 0;
    }

    const int og = lane >> 2;
    const int ot = lane & 3;

    if (MODE == 0 && n0 >= 2 * C_) {
        // V block -> g_vT[B][H*D][T], transposed + tf32-rounded
#pragma unroll
        for (int mt = 0; mt < 4; mt++) {
            int r0 = m0 + warp_m * 64 + mt * 16 + og;
            int bb = r0 >> 11;
            int tt = r0 & (T_ - 1);
#pragma unroll
            for (int nt = 0; nt < 4; nt++) {
                int hd = n0 + warp_n * 32 + nt * 8 + ot * 2 - 2 * C_;
                float* v0p = (float*)g_vT + (size_t)(bb * C_ + hd) * T_;
                float* v1p = v0p + T_;
                v0p[tt]     = __uint_as_float(f2tf32(acc[mt][nt][0]));
                v1p[tt]     = __uint_as_float(f2tf32(acc[mt][nt][1]));
                v0p[tt + 8] = __uint_as_float(f2tf32(acc[mt][nt][2]));
                v1p[tt + 8] = __uint_as_float(f2tf32(acc[mt][nt][3]));
            }
        }
    } else {
        float* Cg = (MODE == 0) ? (float*)g_qkv : Cp;
#pragma unroll
        for (int mt = 0; mt < 4; mt++) {
            int r0 = m0 + warp_m * 64 + mt * 16 + og;
#pragma unroll
            for (int nt = 0; nt < 4; nt++) {
                int col = n0 + warp_n * 32 + nt * 8 + ot * 2;
                float2 lo, hi;
                if (MODE == 0) {
                    lo = { __uint_as_float(f2tf32(acc[mt][nt][0])),
                           __uint_as_float(f2tf32(acc[mt][nt][1])) };
                    hi = { __uint_as_float(f2tf32(acc[mt][nt][2])),
                           __uint_as_float(f2tf32(acc[mt][nt][3])) };
                } else {
                    lo = { acc[mt][nt][0], acc[mt][nt][1] };
                    hi = { acc[mt][nt][2], acc[mt][nt][3] };
                }
                *(float2*)(Cg + (size_t)r0 * N + col) = lo;
                *(float2*)(Cg + (size_t)(r0 + 8) * N + col) = hi;
            }
        }
    }
}

// ===========================================================================
// Tensor-core flash attention (tf32 mma.sync, causal), cp.async 2-stage.
// Q fragments live in registers (pre-scaled/rounded in gmem).
// smem: Ks[2][64][68] | Vt[2][64][68] | Ps[128][68]  = 104448 B, 2 CTAs/SM.
// ===========================================================================
#define FSTR 68
#define KTILE (64 * FSTR * 4)                 // 17408 bytes
#define FLASH3_SMEM_BYTES (4 * KTILE + 128 * FSTR * 4)   // 104448

__device__ __forceinline__ void flash_issue(
    const float* __restrict__ ksrc, const float* __restrict__ vsrc,
    uint32_t ksb, uint32_t vtb, int j0, int tid)
{
#pragma unroll
    for (int jj = 0; jj < 4; jj++) {
        int slot = tid + jj * 256;        // 0..1023
        int r  = slot >> 4;               // 0..63
        int c4 = (slot & 15) << 2;        // 0..60
        uint32_t off = (uint32_t)(r * FSTR + c4) * 4;
        cp_async16(ksb + off, ksrc + (size_t)(j0 + r) * TC3 + c4);
        cp_async16(vtb + off, vsrc + (size_t)r * T_ + j0 + c4);
    }
}

__global__ __launch_bounds__(256, 2) void flash_mma_kernel()
{
    extern __shared__ float smf[];
    const uint32_t smem_u32 = smem_to_u32(smf);
    float* Ps = smf + 4 * KTILE / 4;           // 17408 floats in
    const uint32_t ps_u32 = smem_u32 + 4 * KTILE;

    const float* qkv = (const float*)g_qkv;
    float* att = (float*)g_att;

    const int tid = threadIdx.x;
    const int lane = tid & 31;
    const int w = tid >> 5;
    const int h = blockIdx.y;
    const int b = blockIdx.z;
    const int q0 = (gridDim.x - 1 - blockIdx.x) * 128;
    const int base = b * T_ * TC3;
    const int hoff = h * D_;

    const float* ksrc = qkv + base + hoff;                       // k segment
    const float* vsrc = (const float*)g_vT + (size_t)(b * C_ + hoff) * T_;

    const int a_row = lane & 15;
    const int a_kb  = (lane >> 4) & 1;
    const int b_row = ((lane & 16) >> 1) + (lane & 7);
    const int b_kb  = (lane >> 3) & 1;
    const int g  = lane >> 2;
    const int t  = lane & 3;
    const int t2 = t * 2;

    const int ntiles = (q0 >> 6) + 2;

    // Prologue: tile 0 -> stage 0
    flash_issue(ksrc, vsrc, smem_u32, smem_u32 + KTILE, 0, tid);
    CP_COMMIT();

    // Q fragments: 32 regs, loaded once (q pre-scaled + tf32-rounded in gmem)
    uint32_t qf[8][4];
    {
        const uint32_t* qp = (const uint32_t*)(qkv + base + C_ + hoff);
        const size_t row0 = (size_t)(q0 + w * 16 + g) * TC3;
        const size_t row1 = row0 + (size_t)8 * TC3;
#pragma unroll
        for (int ks = 0; ks < 8; ks++) {
            int c = ks * 8 + t;
            qf[ks][0] = qp[row0 + c];
            qf[ks][1] = qp[row1 + c];
            qf[ks][2] = qp[row0 + c + 4];
            qf[ks][3] = qp[row1 + c + 4];
        }
    }

    float o[8][4];
#pragma unroll
    for (int nt = 0; nt < 8; nt++)
#pragma unroll
        for (int k = 0; k < 4; k++) o[nt][k] = 0.f;
    float m0 = -1e30f, m1 = -1e30f, l0 = 0.f, l1 = 0.f;

    for (int i = 0; i < ntiles; i++) {
        __syncthreads();                  // prev compute done before buffer reuse
        if (i + 1 < ntiles) {
            uint32_t sb = smem_u32 + (uint32_t)((i + 1) & 1) * (2 * KTILE);
            flash_issue(ksrc, vsrc, sb, sb + KTILE, (i + 1) * 64, tid);
            CP_COMMIT();
            CP_WAIT1();                   // tile i resident
        } else {
            CP_WAIT0();
        }
        __syncthreads();                  // cross-thread visibility

        const uint32_t ksb = smem_u32 + (uint32_t)(i & 1) * (2 * KTILE);
        const uint32_t vtb = ksb + KTILE;
        const int j0 = i * 64;

        // S = Q @ K^T
        float s[8][4];
#pragma unroll
        for (int nt = 0; nt < 8; nt++)
#pragma unroll
            for (int k = 0; k < 4; k++) s[nt][k] = 0.f;

#pragma unroll
        for (int ks = 0; ks < 8; ks++) {
            uint32_t bf[4][4];
#pragma unroll
            for (int p = 0; p < 4; p++)
                ldmx4(bf[p], ksb + ((p * 16 + b_row) * FSTR + ks * 8 + b_kb * 4) * 4);
#pragma unroll
            for (int nt = 0; nt < 8; nt++)
                mma_tf32(s[nt], qf[ks], &bf[nt >> 1][(nt & 1) * 2]);
        }

        // Causal mask
        if (j0 + 64 > q0) {
            const int q_lo = q0 + w * 16 + g;
            const int q_hi = q_lo + 8;
#pragma unroll
            for (int nt = 0; nt < 8; nt++) {
                int j = j0 + nt * 8 + t2;
                if (j     > q_lo) s[nt][0] = -1e30f;
                if (j + 1 > q_lo) s[nt][1] = -1e30f;
                if (j     > q_hi) s[nt][2] = -1e30f;
                if (j + 1 > q_hi) s[nt][3] = -1e30f;
            }
        }

        // Online softmax
        float mx0 = -1e30f, mx1 = -1e30f;
#pragma unroll
        for (int nt = 0; nt < 8; nt++) {
            mx0 = fmaxf(mx0, fmaxf(s[nt][0], s[nt][1]));
            mx1 = fmaxf(mx1, fmaxf(s[nt][2], s[nt][3]));
        }
        mx0 = fmaxf(mx0, __shfl_xor_sync(0xffffffffu, mx0, 1));
        mx0 = fmaxf(mx0, __shfl_xor_sync(0xffffffffu, mx0, 2));
        mx1 = fmaxf(mx1, __shfl_xor_sync(0xffffffffu, mx1, 1));
        mx1 = fmaxf(mx1, __shfl_xor_sync(0xffffffffu, mx1, 2));
        const float mn0 = fmaxf(m0, mx0), mn1 = fmaxf(m1, mx1);
        const float al0 = __expf(m0 - mn0), al1 = __expf(m1 - mn1);
        m0 = mn0; m1 = mn1;

        float rs0 = 0.f, rs1 = 0.f;
        uint32_t* PsRow0 = (uint32_t*)Ps + (w * 16 + g) * FSTR;
        uint32_t* PsRow1 = PsRow0 + 8 * FSTR;
#pragma unroll
        for (int nt = 0; nt < 8; nt++) {
            float p00 = __expf(s[nt][0] - mn0);
            float p01 = __expf(s[nt][1] - mn0);
            float p10 = __expf(s[nt][2] - mn1);
            float p11 = __expf(s[nt][3] - mn1);
            rs0 += p00 + p01;
            rs1 += p10 + p11;
            uint2 w0 = { f2tf32(p00), f2tf32(p01) };
            uint2 w1 = { f2tf32(p10), f2tf32(p11) };
            *(uint2*)(PsRow0 + nt * 8 + t2) = w0;
            *(uint2*)(PsRow1 + nt * 8 + t2) = w1;
        }
        rs0 += __shfl_xor_sync(0xffffffffu, rs0, 1);
        rs0 += __shfl_xor_sync(0xffffffffu, rs0, 2);
        rs1 += __shfl_xor_sync(0xffffffffu, rs1, 1);
        rs1 += __shfl_xor_sync(0xffffffffu, rs1, 2);
        l0 = l0 * al0 + rs0;
        l1 = l1 * al1 + rs1;
#pragma unroll
        for (int nt = 0; nt < 8; nt++) {
            o[nt][0] *= al0; o[nt][1] *= al0;
            o[nt][2] *= al1; o[nt][3] *= al1;
        }
        __syncwarp();                      // Ps rows are warp-private

        // O += P @ V
#pragma unroll
        for (int ks = 0; ks < 8; ks++) {
            uint32_t af[4];
            ldmx4(af, ps_u32 + ((w * 16 + a_row) * FSTR + ks * 8 + a_kb * 4) * 4);
            uint32_t bf[4][4];
#pragma unroll
            for (int p = 0; p < 4; p++)
                ldmx4(bf[p], vtb + ((p * 16 + b_row) * FSTR + ks * 8 + b_kb * 4) * 4);
#pragma unroll
            for (int nt = 0; nt < 8; nt++)
                mma_tf32(o[nt], af, &bf[nt >> 1][(nt & 1) * 2]);
        }
    }

    // Epilogue: normalize, round to tf32 (RNA), store
    const float inv0 = 1.f / l0, inv1 = 1.f / l1;
    const int q_lo = q0 + w * 16 + g;
    float* arow0 = att + (size_t)(b * T_ + q_lo) * C_ + hoff;
    float* arow1 = arow0 + (size_t)8 * C_;
#pragma unroll
    for (int nt = 0; nt < 8; nt++) {
        float2 lo = { __uint_as_float(f2tf32(o[nt][0] * inv0)),
                      __uint_as_float(f2tf32(o[nt][1] * inv0)) };
        float2 hi = { __uint_as_float(f2tf32(o[nt][2] * inv1)),
                      __uint_as_float(f2tf32(o[nt][3] * inv1)) };
        *(float2*)(arow0 + nt * 8 + t2) = lo;
        *(float2*)(arow1 + nt * 8 + t2) = hi;
    }
}

// ===========================================================================
// Launch
// ===========================================================================
extern "C" void kernel_launch(void* const* d_in, const int* in_sizes, int n_in,
                              void* d_out, int out_size)
{
    const float* x     = (const float*)d_in[0];   // [B,T,C]
    const float* Wqkv  = (const float*)d_in[1];   // [C,3C]
    const float* Wproj = (const float*)d_in[2];   // [C,C]
    float* out = (float*)d_out;                   // [B,T,C]

    cudaFuncSetAttribute(flash_mma_kernel,
                         cudaFuncAttributeMaxDynamicSharedMemorySize,
                         FLASH3_SMEM_BYTES);
    cudaFuncSetAttribute(mma_gemm2<0, TC3, C_>,
                         cudaFuncAttributeMaxDynamicSharedMemorySize, G2_SMEM);
    cudaFuncSetAttribute(mma_gemm2<1, C_, C_>,
                         cudaFuncAttributeMaxDynamicSharedMemorySize, G2_SMEM);

    // 0) Pre-round x; transpose+round weights (q-rows pre-scaled)
    round_x_kernel<<<512, 256>>>(x);
    transpose_kernel<0><<<dim3(TC3 / 32, C_ / 32), dim3(32, 8)>>>(Wqkv, C_, TC3);
    transpose_kernel<1><<<dim3(C_ / 32, C_ / 32), dim3(32, 8)>>>(Wproj, C_, C_);

    // 1) k,q -> g_qkv; v -> g_vT (transposed)
    mma_gemm2<0, TC3, C_><<<dim3(TC3 / 128, (B_ * T_) / 128), 256, G2_SMEM>>>(nullptr);

    // 2) flash attention: g_qkv(k,q) + g_vT -> g_att
    flash_mma_kernel<<<dim3(T_ / 128, H_, B_), 256, FLASH3_SMEM_BYTES>>>();

    // 3) out = g_att @ W_proj
    mma_gemm2<1, C_, C_><<<dim3(C_ / 128, (B_ * T_) / 128), 256, G2_SMEM>>>(out);
}

// round 13
// speedup vs baseline: 7.3007x; 1.7552x over previous
#include <cuda_runtime.h>
#include <cuda_fp16.h>
#include <cstdint>

// Problem constants
#define B_   4
#define T_   2048
#define C_   1024
#define H_   16
#define D_   64
#define TC3  (3 * C_)

// Scratch (allocation-free rule: __device__ globals), fp16 pipeline
__device__ __half g_qkv[B_ * T_ * TC3];    // [B,T,3C] k|q (v slot unused), q pre-scaled
__device__ __half g_vT[B_ * C_ * T_];      // [B][H*D][T]  V transposed
__device__ __half g_att[B_ * T_ * C_];     // [B,T,C]
__device__ __half g_xh[B_ * T_ * C_];      // [B,T,C]  x rounded to fp16
__device__ __half g_WqkvT[TC3 * C_];       // [3C, C] = W_qkv^T, q-rows pre-scaled
__device__ __half g_WprojT[C_ * C_];       // [C, C]  = W_proj^T

// ===========================================================================
// Helpers
// ===========================================================================
__device__ __forceinline__ uint32_t smem_to_u32(const void* p) {
    uint32_t a;
    asm("{ .reg .u64 t; cvta.to.shared.u64 t, %1; cvt.u32.u64 %0, t; }"
        : "=r"(a) : "l"(p));
    return a;
}

__device__ __forceinline__ void ldmx4(uint32_t* r, uint32_t addr) {
    asm volatile("ldmatrix.sync.aligned.m8n8.x4.shared.b16 {%0,%1,%2,%3}, [%4];"
                 : "=r"(r[0]), "=r"(r[1]), "=r"(r[2]), "=r"(r[3]) : "r"(addr));
}

__device__ __forceinline__ void mma_f16(float* c, const uint32_t* a,
                                        const uint32_t* b) {
    asm volatile(
        "mma.sync.aligned.m16n8k16.row.col.f32.f16.f16.f32 "
        "{%0,%1,%2,%3}, {%4,%5,%6,%7}, {%8,%9}, {%0,%1,%2,%3};"
        : "+f"(c[0]), "+f"(c[1]), "+f"(c[2]), "+f"(c[3])
        : "r"(a[0]), "r"(a[1]), "r"(a[2]), "r"(a[3]), "r"(b[0]), "r"(b[1]));
}

__device__ __forceinline__ void cp_async16(uint32_t smem_dst, const void* gsrc) {
    asm volatile("cp.async.cg.shared.global [%0], [%1], 16;"
                 :: "r"(smem_dst), "l"(gsrc));
}
#define CP_COMMIT() asm volatile("cp.async.commit_group;" ::: "memory")
#define CP_WAIT1()  asm volatile("cp.async.wait_group 1;" ::: "memory")
#define CP_WAIT0()  asm volatile("cp.async.wait_group 0;" ::: "memory")

#define SWZ(off) ((off) ^ (((off) >> 3) & 0x70))

__device__ __forceinline__ uint32_t h2u(__half2 h) {
    return *(uint32_t*)&h;
}

// ===========================================================================
// Round x to fp16 -> g_xh
// ===========================================================================
__global__ void round_x_kernel(const float* __restrict__ x)
{
    const int n8 = (B_ * T_ * C_) / 8;
    for (int i = blockIdx.x * blockDim.x + threadIdx.x; i < n8;
         i += gridDim.x * blockDim.x) {
        float4 v0 = ((const float4*)x)[2 * i];
        float4 v1 = ((const float4*)x)[2 * i + 1];
        uint4 o = { h2u(__floats2half2_rn(v0.x, v0.y)),
                    h2u(__floats2half2_rn(v0.z, v0.w)),
                    h2u(__floats2half2_rn(v1.x, v1.y)),
                    h2u(__floats2half2_rn(v1.z, v1.w)) };
        ((uint4*)g_xh)[i] = o;
    }
}

// ===========================================================================
// Weight transpose + fp16 round. MODE 0 scales q-rows (C..2C-1) by 2^-5.
// ===========================================================================
template <int MODE>
__global__ void transpose_kernel(const float* __restrict__ in, int R, int Cc)
{
    __shared__ float t[32][33];
    __half* out = (MODE == 0) ? (__half*)g_WqkvT : (__half*)g_WprojT;
    const int c0 = blockIdx.x * 32, r0 = blockIdx.y * 32;
#pragma unroll
    for (int j = threadIdx.y; j < 32; j += 8)
        t[j][threadIdx.x] = in[(size_t)(r0 + j) * Cc + c0 + threadIdx.x];
    __syncthreads();
#pragma unroll
    for (int j = threadIdx.y; j < 32; j += 8) {
        int orow = c0 + j;
        float v = t[threadIdx.x][j];
        if (MODE == 0 && orow >= C_ && orow < 2 * C_) v *= 0.03125f;
        out[(size_t)orow * R + r0 + threadIdx.x] = __float2half_rn(v);
    }
}

// ===========================================================================
// fp16 tensor-core GEMM, cp.async 3-stage pipeline.
// C[M,N] = A[M,K] @ Bt[N,K]^T. Stage tile: 128 rows x 128B (K=64 fp16), SW128.
// MODE 0: A=g_xh, Bt=g_WqkvT; k,q -> g_qkv; v -> g_vT transposed.
// MODE 1: A=g_att, Bt=g_WprojT; C = param out (fp32).
// ===========================================================================
#define G2_STAGES 3
#define G2_TILE   16384
#define G2_STAGE_BYTES (2 * G2_TILE)
#define G2_SMEM   (G2_STAGES * G2_STAGE_BYTES)   // 98304

template <int K>
__device__ __forceinline__ void g2_issue(
    const __half* __restrict__ Ag, const __half* __restrict__ Bg,
    uint32_t Abuf, uint32_t Bbuf, int m0, int n0, int k0, int tid)
{
#pragma unroll
    for (int j = 0; j < 4; j++) {
        int slot = tid + j * 256;
        int row = slot >> 3;
        int f8  = slot & 7;                // 16B = 8 fp16
        uint32_t off = SWZ(row * 128 + f8 * 16);
        cp_async16(Abuf + off, Ag + (size_t)(m0 + row) * K + k0 + f8 * 8);
        cp_async16(Bbuf + off, Bg + (size_t)(n0 + row) * K + k0 + f8 * 8);
    }
}

template <int MODE, int N, int K>
__global__ __launch_bounds__(256, 2) void mma_gemm2(float* __restrict__ Cp)
{
    extern __shared__ char sm[];
    const uint32_t smem_u32 = smem_to_u32(sm);

    const __half* Ag = (MODE == 0) ? (const __half*)g_xh : (const __half*)g_att;
    const __half* Bg = (MODE == 0) ? (const __half*)g_WqkvT : (const __half*)g_WprojT;

    const int tid = threadIdx.x;
    const int lane = tid & 31;
    const int wid = tid >> 5;
    const int warp_m = wid & 1;
    const int warp_n = wid >> 1;
    const int m0 = blockIdx.y * 128;
    const int n0 = blockIdx.x * 128;

    float acc[4][4][4];
#pragma unroll
    for (int i = 0; i < 4; i++)
#pragma unroll
        for (int j = 0; j < 4; j++)
#pragma unroll
            for (int k = 0; k < 4; k++) acc[i][j][k] = 0.f;

    const int NCHUNK = K / 64;             // 16

    g2_issue<K>(Ag, Bg, smem_u32, smem_u32 + G2_TILE, m0, n0, 0, tid);
    CP_COMMIT();
    g2_issue<K>(Ag, Bg, smem_u32 + G2_STAGE_BYTES,
                smem_u32 + G2_STAGE_BYTES + G2_TILE, m0, n0, 64, tid);
    CP_COMMIT();

    const int a_row_in_tile = lane & 15;
    const int a_kblk = (lane >> 4) & 1;
    const int b_row_in_pair = ((lane & 16) >> 1) + (lane & 7);
    const int b_kblk = (lane >> 3) & 1;

    int st = 0;
    for (int i = 0; i < NCHUNK; i++) {
        CP_WAIT1();
        __syncthreads();

        if (i + 2 < NCHUNK) {
            int sn = st + 2; if (sn >= G2_STAGES) sn -= G2_STAGES;
            uint32_t base = smem_u32 + (uint32_t)sn * G2_STAGE_BYTES;
            g2_issue<K>(Ag, Bg, base, base + G2_TILE, m0, n0, (i + 2) * 64, tid);
        }
        CP_COMMIT();

        const uint32_t Abuf = smem_u32 + (uint32_t)st * G2_STAGE_BYTES;
        const uint32_t Bbuf = Abuf + G2_TILE;
#pragma unroll
        for (int ks = 0; ks < 4; ks++) {   // 4 k16-steps per 64-K chunk
            uint32_t afr[4][4];
#pragma unroll
            for (int mt = 0; mt < 4; mt++) {
                int row = warp_m * 64 + mt * 16 + a_row_in_tile;
                ldmx4(afr[mt], Abuf + SWZ(row * 128 + ks * 32 + a_kblk * 16));
            }
            uint32_t bfr[2][4];
#pragma unroll
            for (int p = 0; p < 2; p++) {
                int row = warp_n * 32 + p * 16 + b_row_in_pair;
                ldmx4(bfr[p], Bbuf + SWZ(row * 128 + ks * 32 + b_kblk * 16));
            }
#pragma unroll
            for (int mt = 0; mt < 4; mt++)
#pragma unroll
                for (int nt = 0; nt < 4; nt++)
                    mma_f16(acc[mt][nt], afr[mt], &bfr[nt >> 1][(nt & 1) * 2]);
        }

        if (++st == G2_STAGES) st = 0;
    }

    const int og = lane >> 2;
    const int ot = lane & 3;

    if (MODE == 0 && n0 >= 2 * C_) {
        // V block -> g_vT[B][H*D][T], transposed + fp16
#pragma unroll
        for (int mt = 0; mt < 4; mt++) {
            int r0 = m0 + warp_m * 64 + mt * 16 + og;
            int bb = r0 >> 11;
            int tt = r0 & (T_ - 1);
#pragma unroll
            for (int nt = 0; nt < 4; nt++) {
                int hd = n0 + warp_n * 32 + nt * 8 + ot * 2 - 2 * C_;
                __half* v0p = (__half*)g_vT + (size_t)(bb * C_ + hd) * T_;
                __half* v1p = v0p + T_;
                v0p[tt]     = __float2half_rn(acc[mt][nt][0]);
                v1p[tt]     = __float2half_rn(acc[mt][nt][1]);
                v0p[tt + 8] = __float2half_rn(acc[mt][nt][2]);
                v1p[tt + 8] = __float2half_rn(acc[mt][nt][3]);
            }
        }
    } else if (MODE == 0) {
        __half* Cg = (__half*)g_qkv;
#pragma unroll
        for (int mt = 0; mt < 4; mt++) {
            int r0 = m0 + warp_m * 64 + mt * 16 + og;
#pragma unroll
            for (int nt = 0; nt < 4; nt++) {
                int col = n0 + warp_n * 32 + nt * 8 + ot * 2;
                *(__half2*)(Cg + (size_t)r0 * N + col) =
                    __floats2half2_rn(acc[mt][nt][0], acc[mt][nt][1]);
                *(__half2*)(Cg + (size_t)(r0 + 8) * N + col) =
                    __floats2half2_rn(acc[mt][nt][2], acc[mt][nt][3]);
            }
        }
    } else {
#pragma unroll
        for (int mt = 0; mt < 4; mt++) {
            int r0 = m0 + warp_m * 64 + mt * 16 + og;
#pragma unroll
            for (int nt = 0; nt < 4; nt++) {
                int col = n0 + warp_n * 32 + nt * 8 + ot * 2;
                float2 lo = { acc[mt][nt][0], acc[mt][nt][1] };
                float2 hi = { acc[mt][nt][2], acc[mt][nt][3] };
                *(float2*)(Cp + (size_t)r0 * N + col) = lo;
                *(float2*)(Cp + (size_t)(r0 + 8) * N + col) = hi;
            }
        }
    }
}

// ===========================================================================
// fp16 tensor-core flash attention (causal), cp.async 2-stage.
// Q fragments in registers. smem rows = 64 fp16 + 8 pad = 144B stride
// (rows advance 9 16B-banks -> conflict-free LDSM).
// Layout: Ks[2][64][144B] | Vt[2][64][144B] | Ps[128][144B] = 55296 B.
// ===========================================================================
#define FROWB 144
#define KTILE (64 * FROWB)                    // 9216 bytes
#define FLASH4_SMEM_BYTES (4 * KTILE + 128 * FROWB)   // 55296

__device__ __forceinline__ void flash_issue(
    const __half* __restrict__ ksrc, const __half* __restrict__ vsrc,
    uint32_t ksb, uint32_t vtb, int j0, int tid)
{
#pragma unroll
    for (int jj = 0; jj < 2; jj++) {
        int slot = tid + jj * 256;         // 0..511
        int r  = slot >> 3;                // 0..63
        int c8 = slot & 7;                 // 16B chunk (8 fp16)
        uint32_t off = (uint32_t)(r * FROWB + c8 * 16);
        cp_async16(ksb + off, ksrc + (size_t)(j0 + r) * TC3 + c8 * 8);
        cp_async16(vtb + off, vsrc + (size_t)r * T_ + j0 + c8 * 8);
    }
}

__global__ __launch_bounds__(256, 2) void flash_mma_kernel()
{
    extern __shared__ char smb[];
    const uint32_t smem_u32 = smem_to_u32(smb);
    const uint32_t ps_u32 = smem_u32 + 4 * KTILE;
    char* PsB = smb + 4 * KTILE;

    const __half* qkv = (const __half*)g_qkv;
    __half* att = (__half*)g_att;

    const int tid = threadIdx.x;
    const int lane = tid & 31;
    const int w = tid >> 5;
    const int h = blockIdx.y;
    const int b = blockIdx.z;
    const int q0 = (gridDim.x - 1 - blockIdx.x) * 128;
    const int base = b * T_ * TC3;
    const int hoff = h * D_;

    const __half* ksrc = qkv + base + hoff;
    const __half* vsrc = (const __half*)g_vT + (size_t)(b * C_ + hoff) * T_;

    const int a_row = lane & 15;
    const int a_kb  = (lane >> 4) & 1;
    const int b_row = ((lane & 16) >> 1) + (lane & 7);
    const int b_kb  = (lane >> 3) & 1;
    const int g  = lane >> 2;
    const int t  = lane & 3;
    const int t2 = t * 2;

    const int ntiles = (q0 >> 6) + 2;

    flash_issue(ksrc, vsrc, smem_u32, smem_u32 + KTILE, 0, tid);
    CP_COMMIT();

    // Q fragments: 16 regs (4 k16-steps x 4), q pre-scaled fp16 in gmem
    uint32_t qf[4][4];
    {
        const __half* qp = qkv + base + C_ + hoff;
        const size_t row0 = (size_t)(q0 + w * 16 + g) * TC3;
        const size_t row1 = row0 + (size_t)8 * TC3;
#pragma unroll
        for (int ks = 0; ks < 4; ks++) {
            int c = ks * 16 + t2;
            qf[ks][0] = *(const uint32_t*)(qp + row0 + c);
            qf[ks][1] = *(const uint32_t*)(qp + row1 + c);
            qf[ks][2] = *(const uint32_t*)(qp + row0 + c + 8);
            qf[ks][3] = *(const uint32_t*)(qp + row1 + c + 8);
        }
    }

    float o[8][4];
#pragma unroll
    for (int nt = 0; nt < 8; nt++)
#pragma unroll
        for (int k = 0; k < 4; k++) o[nt][k] = 0.f;
    float m0 = -1e30f, m1 = -1e30f, l0 = 0.f, l1 = 0.f;

    for (int i = 0; i < ntiles; i++) {
        __syncthreads();
        if (i + 1 < ntiles) {
            uint32_t sb = smem_u32 + (uint32_t)((i + 1) & 1) * (2 * KTILE);
            flash_issue(ksrc, vsrc, sb, sb + KTILE, (i + 1) * 64, tid);
            CP_COMMIT();
            CP_WAIT1();
        } else {
            CP_WAIT0();
        }
        __syncthreads();

        const uint32_t ksb = smem_u32 + (uint32_t)(i & 1) * (2 * KTILE);
        const uint32_t vtb = ksb + KTILE;
        const int j0 = i * 64;

        // S = Q @ K^T  (4 k16-steps over D=64)
        float s[8][4];
#pragma unroll
        for (int nt = 0; nt < 8; nt++)
#pragma unroll
            for (int k = 0; k < 4; k++) s[nt][k] = 0.f;

#pragma unroll
        for (int ks = 0; ks < 4; ks++) {
            uint32_t bf[4][4];
#pragma unroll
            for (int p = 0; p < 4; p++)
                ldmx4(bf[p], ksb + (p * 16 + b_row) * FROWB + ks * 32 + b_kb * 16);
#pragma unroll
            for (int nt = 0; nt < 8; nt++)
                mma_f16(s[nt], qf[ks], &bf[nt >> 1][(nt & 1) * 2]);
        }

        // Causal mask
        if (j0 + 64 > q0) {
            const int q_lo = q0 + w * 16 + g;
            const int q_hi = q_lo + 8;
#pragma unroll
            for (int nt = 0; nt < 8; nt++) {
                int j = j0 + nt * 8 + t2;
                if (j     > q_lo) s[nt][0] = -1e30f;
                if (j + 1 > q_lo) s[nt][1] = -1e30f;
                if (j     > q_hi) s[nt][2] = -1e30f;
                if (j + 1 > q_hi) s[nt][3] = -1e30f;
            }
        }

        // Online softmax
        float mx0 = -1e30f, mx1 = -1e30f;
#pragma unroll
        for (int nt = 0; nt < 8; nt++) {
            mx0 = fmaxf(mx0, fmaxf(s[nt][0], s[nt][1]));
            mx1 = fmaxf(mx1, fmaxf(s[nt][2], s[nt][3]));
        }
        mx0 = fmaxf(mx0, __shfl_xor_sync(0xffffffffu, mx0, 1));
        mx0 = fmaxf(mx0, __shfl_xor_sync(0xffffffffu, mx0, 2));
        mx1 = fmaxf(mx1, __shfl_xor_sync(0xffffffffu, mx1, 1));
        mx1 = fmaxf(mx1, __shfl_xor_sync(0xffffffffu, mx1, 2));
        const float mn0 = fmaxf(m0, mx0), mn1 = fmaxf(m1, mx1);
        const float al0 = __expf(m0 - mn0), al1 = __expf(m1 - mn1);
        m0 = mn0; m1 = mn1;

        float rs0 = 0.f, rs1 = 0.f;
        char* PsRow0 = PsB + (w * 16 + g) * FROWB;
        char* PsRow1 = PsRow0 + 8 * FROWB;
#pragma unroll
        for (int nt = 0; nt < 8; nt++) {
            float p00 = __expf(s[nt][0] - mn0);
            float p01 = __expf(s[nt][1] - mn0);
            float p10 = __expf(s[nt][2] - mn1);
            float p11 = __expf(s[nt][3] - mn1);
            rs0 += p00 + p01;
            rs1 += p10 + p11;
            *(uint32_t*)(PsRow0 + (nt * 8 + t2) * 2) = h2u(__floats2half2_rn(p00, p01));
            *(uint32_t*)(PsRow1 + (nt * 8 + t2) * 2) = h2u(__floats2half2_rn(p10, p11));
        }
        rs0 += __shfl_xor_sync(0xffffffffu, rs0, 1);
        rs0 += __shfl_xor_sync(0xffffffffu, rs0, 2);
        rs1 += __shfl_xor_sync(0xffffffffu, rs1, 1);
        rs1 += __shfl_xor_sync(0xffffffffu, rs1, 2);
        l0 = l0 * al0 + rs0;
        l1 = l1 * al1 + rs1;
#pragma unroll
        for (int nt = 0; nt < 8; nt++) {
            o[nt][0] *= al0; o[nt][1] *= al0;
            o[nt][2] *= al1; o[nt][3] *= al1;
        }
        __syncwarp();                      // Ps rows are warp-private

        // O += P @ V  (4 k16-steps over 64 keys)
#pragma unroll
        for (int ks = 0; ks < 4; ks++) {
            uint32_t af[4];
            ldmx4(af, ps_u32 + (w * 16 + a_row) * FROWB + ks * 32 + a_kb * 16);
            uint32_t bf[4][4];
#pragma unroll
            for (int p = 0; p < 4; p++)
                ldmx4(bf[p], vtb + (p * 16 + b_row) * FROWB + ks * 32 + b_kb * 16);
#pragma unroll
            for (int nt = 0; nt < 8; nt++)
                mma_f16(o[nt], af, &bf[nt >> 1][(nt & 1) * 2]);
        }
    }

    // Epilogue: normalize, round to fp16, store
    const float inv0 = 1.f / l0, inv1 = 1.f / l1;
    const int q_lo = q0 + w * 16 + g;
    __half* arow0 = att + (size_t)(b * T_ + q_lo) * C_ + hoff;
    __half* arow1 = arow0 + (size_t)8 * C_;
#pragma unroll
    for (int nt = 0; nt < 8; nt++) {
        *(__half2*)(arow0 + nt * 8 + t2) =
            __floats2half2_rn(o[nt][0] * inv0, o[nt][1] * inv0);
        *(__half2*)(arow1 + nt * 8 + t2) =
            __floats2half2_rn(o[nt][2] * inv1, o[nt][3] * inv1);
    }
}

// ===========================================================================
// Launch
// ===========================================================================
extern "C" void kernel_launch(void* const* d_in, const int* in_sizes, int n_in,
                              void* d_out, int out_size)
{
    const float* x     = (const float*)d_in[0];   // [B,T,C]
    const float* Wqkv  = (const float*)d_in[1];   // [C,3C]
    const float* Wproj = (const float*)d_in[2];   // [C,C]
    float* out = (float*)d_out;                   // [B,T,C]

    cudaFuncSetAttribute(flash_mma_kernel,
                         cudaFuncAttributeMaxDynamicSharedMemorySize,
                         FLASH4_SMEM_BYTES);
    cudaFuncSetAttribute(mma_gemm2<0, TC3, C_>,
                         cudaFuncAttributeMaxDynamicSharedMemorySize, G2_SMEM);
    cudaFuncSetAttribute(mma_gemm2<1, C_, C_>,
                         cudaFuncAttributeMaxDynamicSharedMemorySize, G2_SMEM);

    // 0) Round x to fp16; transpose+round weights (q-rows pre-scaled)
    round_x_kernel<<<512, 256>>>(x);
    transpose_kernel<0><<<dim3(TC3 / 32, C_ / 32), dim3(32, 8)>>>(Wqkv, C_, TC3);
    transpose_kernel<1><<<dim3(C_ / 32, C_ / 32), dim3(32, 8)>>>(Wproj, C_, C_);

    // 1) k,q -> g_qkv; v -> g_vT (transposed)   (fp16 mma)
    mma_gemm2<0, TC3, C_><<<dim3(TC3 / 128, (B_ * T_) / 128), 256, G2_SMEM>>>(nullptr);

    // 2) flash attention: g_qkv(k,q) + g_vT -> g_att   (fp16 mma)
    flash_mma_kernel<<<dim3(T_ / 128, H_, B_), 256, FLASH4_SMEM_BYTES>>>();

    // 3) out = g_att @ W_proj   (fp16 mma, fp32 out)
    mma_gemm2<1, C_, C_><<<dim3(C_ / 128, (B_ * T_) / 128), 256, G2_SMEM>>>(out);
}